// round 1
// baseline (speedup 1.0000x reference)
#include <cuda_runtime.h>
#include <cuda_bf16.h>
#include <math.h>

// ---------------------------------------------------------------------------
// Problem constants: B=2, S=2048, HID=2048, NH=16, HD=128, fp32 everywhere.
// ---------------------------------------------------------------------------
#define BATCH 2
#define SEQ   2048
#define HID   2048
#define NH    16
#define HD    128
#define MROWS (BATCH * SEQ)          // 4096
#define EPS   1e-6f

// ---------------------------------------------------------------------------
// Scratch (device globals; allocation inside kernel_launch is forbidden)
// ---------------------------------------------------------------------------
__device__ float g_xn [MROWS * HID];
__device__ float g_q  [MROWS * HID];
__device__ float g_k  [MROWS * HID];
__device__ float g_v  [MROWS * HID];
__device__ float g_ctx[MROWS * HID];
__device__ float g_h  [MROWS * HID];
__device__ float g_yn [MROWS * HID];
__device__ float g_g1 [MROWS * HID];
__device__ float g_g3 [MROWS * HID];
__device__ float g_t  [MROWS * HID];
__device__ float g_cos[SEQ * (HD / 2)];
__device__ float g_sin[SEQ * (HD / 2)];

// ---------------------------------------------------------------------------
// RMSNorm: one block per row (2048 elems), fp32.
// ---------------------------------------------------------------------------
__global__ void __launch_bounds__(256) rmsnorm_kernel(
    const float* __restrict__ x, const float* __restrict__ w,
    float* __restrict__ y) {
  int row = blockIdx.x;
  const float4* x4 = (const float4*)(x + (size_t)row * HID);
  const float4* w4 = (const float4*)w;
  float4*       y4 = (float4*)(y + (size_t)row * HID);
  int tid = threadIdx.x;

  float s = 0.f;
#pragma unroll
  for (int i = tid; i < HID / 4; i += 256) {
    float4 v = x4[i];
    s += v.x * v.x + v.y * v.y + v.z * v.z + v.w * v.w;
  }
#pragma unroll
  for (int off = 16; off > 0; off >>= 1)
    s += __shfl_xor_sync(0xffffffffu, s, off);

  __shared__ float red[8];
  __shared__ float s_inv;
  if ((tid & 31) == 0) red[tid >> 5] = s;
  __syncthreads();
  if (tid == 0) {
    float t = 0.f;
#pragma unroll
    for (int i = 0; i < 8; i++) t += red[i];
    s_inv = rsqrtf(t / (float)HID + EPS);
  }
  __syncthreads();
  float inv = s_inv;

#pragma unroll
  for (int i = tid; i < HID / 4; i += 256) {
    float4 v = x4[i];
    float4 ww = w4[i];
    float4 o;
    o.x = v.x * inv * ww.x;
    o.y = v.y * inv * ww.y;
    o.z = v.z * inv * ww.z;
    o.w = v.w * inv * ww.w;
    y4[i] = o;
  }
}

// ---------------------------------------------------------------------------
// SGEMM: C[M,N] = A[M,K] @ W[K,N]  (+ D optionally).  M=4096, N=K=2048.
// 128x128 block tile, BK=8, 8x8 per thread, 256 threads.
// ---------------------------------------------------------------------------
#define GN 2048
#define GK 2048

template <bool ADD>
__global__ void __launch_bounds__(256) sgemm_kernel(
    const float* __restrict__ A, const float* __restrict__ W,
    const float* __restrict__ D, float* __restrict__ C) {
  __shared__ float As[8][128];
  __shared__ float Bs[8][128];

  int m0 = blockIdx.y * 128;
  int n0 = blockIdx.x * 128;
  int tid = threadIdx.x;
  int tx = tid & 15;        // 0..15 (col group)
  int ty = tid >> 4;        // 0..15 (row group)

  int arow = tid >> 1;           // 0..127
  int acol = (tid & 1) * 4;      // 0 or 4
  int brow = tid >> 5;           // 0..7
  int bcol = (tid & 31) * 4;     // 0..124

  const float* Aptr = A + (size_t)(m0 + arow) * GK + acol;
  const float* Wptr = W + (size_t)brow * GN + n0 + bcol;

  float acc[8][8];
#pragma unroll
  for (int i = 0; i < 8; i++)
#pragma unroll
    for (int j = 0; j < 8; j++) acc[i][j] = 0.f;

  for (int k0 = 0; k0 < GK; k0 += 8) {
    float4 av = *(const float4*)(Aptr + k0);
    float4 bv = *(const float4*)(Wptr + (size_t)k0 * GN);
    __syncthreads();
    As[acol + 0][arow] = av.x;
    As[acol + 1][arow] = av.y;
    As[acol + 2][arow] = av.z;
    As[acol + 3][arow] = av.w;
    *(float4*)&Bs[brow][bcol] = bv;
    __syncthreads();

#pragma unroll
    for (int kk = 0; kk < 8; kk++) {
      float ra[8], rb[8];
      *(float4*)(ra)     = *(const float4*)&As[kk][ty * 8];
      *(float4*)(ra + 4) = *(const float4*)&As[kk][ty * 8 + 4];
      *(float4*)(rb)     = *(const float4*)&Bs[kk][tx * 8];
      *(float4*)(rb + 4) = *(const float4*)&Bs[kk][tx * 8 + 4];
#pragma unroll
      for (int i = 0; i < 8; i++)
#pragma unroll
        for (int j = 0; j < 8; j++) acc[i][j] += ra[i] * rb[j];
    }
  }

#pragma unroll
  for (int i = 0; i < 8; i++) {
    size_t off = (size_t)(m0 + ty * 8 + i) * GN + n0 + tx * 8;
    float4 r0 = make_float4(acc[i][0], acc[i][1], acc[i][2], acc[i][3]);
    float4 r1 = make_float4(acc[i][4], acc[i][5], acc[i][6], acc[i][7]);
    if (ADD) {
      float4 d0 = *(const float4*)(D + off);
      float4 d1 = *(const float4*)(D + off + 4);
      r0.x += d0.x; r0.y += d0.y; r0.z += d0.z; r0.w += d0.w;
      r1.x += d1.x; r1.y += d1.y; r1.z += d1.z; r1.w += d1.w;
    }
    *(float4*)(C + off)     = r0;
    *(float4*)(C + off + 4) = r1;
  }
}

// ---------------------------------------------------------------------------
// RoPE table: cos/sin(s * invfreq[d]) for s in [0,2048), d in [0,64).
// Mirrors jax: inv_freq = 1 / (10000 ** (d/64)).
// ---------------------------------------------------------------------------
__global__ void rope_table_kernel() {
  int idx = blockIdx.x * 256 + threadIdx.x;   // 131072 total
  int s = idx >> 6;
  int d = idx & 63;
  float invf = 1.0f / powf(10000.0f, (float)d / 64.0f);
  float ang = (float)s * invf;
  g_cos[idx] = cosf(ang);
  g_sin[idx] = sinf(ang);
}

// ---------------------------------------------------------------------------
// RoPE apply (in place on q and k): rotate-half form.
// One thread per (row, head, d<64) pair => 4096*16*64 threads.
// ---------------------------------------------------------------------------
__global__ void __launch_bounds__(256) rope_apply_kernel(
    float* __restrict__ q, float* __restrict__ k) {
  int idx = blockIdx.x * 256 + threadIdx.x;
  int d = idx & 63;
  int h = (idx >> 6) & 15;
  int row = idx >> 10;            // 0..4095
  int s = row & (SEQ - 1);

  float c  = g_cos[s * 64 + d];
  float sn = g_sin[s * 64 + d];
  size_t base = (size_t)row * HID + h * HD + d;

  float q1 = q[base], q2 = q[base + 64];
  q[base]      = q1 * c - q2 * sn;
  q[base + 64] = q2 * c + q1 * sn;

  float k1 = k[base], k2 = k[base + 64];
  k[base]      = k1 * c - k2 * sn;
  k[base + 64] = k2 * c + k1 * sn;
}

// ---------------------------------------------------------------------------
// Flash attention (non-causal, fp32). BM=BN=64, HD=128, 256 threads.
// Q/K stored transposed in smem (pad 65); scores micro-tile 4x4;
// PV micro-tile 4x8; online softmax per-row with 16-lane shfl reductions.
// ---------------------------------------------------------------------------
#define FL_SD 65                      // padded row stride for transposed tiles
#define FL_SMEM_FLOATS (128 * FL_SD * 2 + 64 * 128 + 64 * FL_SD)

__global__ void __launch_bounds__(256) flash_kernel(
    const float* __restrict__ q, const float* __restrict__ k,
    const float* __restrict__ v, float* __restrict__ o) {
  extern __shared__ float sm[];
  float* Qs = sm;                        // [128][65] : Qs[kk][m]
  float* Ks = Qs + 128 * FL_SD;          // [128][65] : Ks[kk][j]
  float* Vs = Ks + 128 * FL_SD;          // [64][128] : Vs[j][n]
  float* Ps = Vs + 64 * 128;             // [64][65]  : Ps[j][m]

  int qb = blockIdx.x;                   // 0..31 query block
  int bh = blockIdx.y;                   // 0..31 (b*NH + h)
  int b = bh >> 4, h = bh & 15;
  int tid = threadIdx.x;
  int ti = tid >> 4;                     // 0..15 : q-row group (4 rows)
  int tj = tid & 15;                     // 0..15 : col group

  size_t rowbase = (size_t)b * SEQ * HID + (size_t)h * HD;
  int q0 = qb * 64;

  // Load Q tile transposed: Qs[c][r] = Q[q0+r][c]
#pragma unroll
  for (int it = 0; it < 8; it++) {
    int e = it * 1024 + tid * 4;
    int r = e >> 7, c = e & 127;
    float4 val = *(const float4*)(q + rowbase + (size_t)(q0 + r) * HID + c);
    Qs[(c + 0) * FL_SD + r] = val.x;
    Qs[(c + 1) * FL_SD + r] = val.y;
    Qs[(c + 2) * FL_SD + r] = val.z;
    Qs[(c + 3) * FL_SD + r] = val.w;
  }

  float O[4][8];
  float mprev[4], lsum[4];
#pragma unroll
  for (int i = 0; i < 4; i++) {
    mprev[i] = -INFINITY;
    lsum[i] = 0.f;
#pragma unroll
    for (int n = 0; n < 8; n++) O[i][n] = 0.f;
  }
  const float scale = 0.08838834764831845f;  // 1/sqrt(128)

  for (int nb = 0; nb < SEQ / 64; nb++) {
    int k0 = nb * 64;
    __syncthreads();   // previous PV reads of Vs / score reads of Ks done
#pragma unroll
    for (int it = 0; it < 8; it++) {
      int e = it * 1024 + tid * 4;
      int r = e >> 7, c = e & 127;
      float4 kv = *(const float4*)(k + rowbase + (size_t)(k0 + r) * HID + c);
      Ks[(c + 0) * FL_SD + r] = kv.x;
      Ks[(c + 1) * FL_SD + r] = kv.y;
      Ks[(c + 2) * FL_SD + r] = kv.z;
      Ks[(c + 3) * FL_SD + r] = kv.w;
      float4 vv = *(const float4*)(v + rowbase + (size_t)(k0 + r) * HID + c);
      *(float4*)&Vs[r * 128 + c] = vv;
    }
    __syncthreads();

    // scores: acc[i][j] = Q[q0+4ti+i] . K[k0+4tj+j]
    float acc[4][4];
#pragma unroll
    for (int i = 0; i < 4; i++)
#pragma unroll
      for (int j = 0; j < 4; j++) acc[i][j] = 0.f;

#pragma unroll 8
    for (int kk = 0; kk < 128; kk++) {
      float ra[4], rb[4];
#pragma unroll
      for (int i = 0; i < 4; i++) ra[i] = Qs[kk * FL_SD + ti * 4 + i];
#pragma unroll
      for (int j = 0; j < 4; j++) rb[j] = Ks[kk * FL_SD + tj * 4 + j];
#pragma unroll
      for (int i = 0; i < 4; i++)
#pragma unroll
        for (int j = 0; j < 4; j++) acc[i][j] += ra[i] * rb[j];
    }

    // online softmax update, per q-row i (reduce across 16 lanes sharing ti)
#pragma unroll
    for (int i = 0; i < 4; i++) {
      float s0 = acc[i][0] * scale, s1 = acc[i][1] * scale;
      float s2 = acc[i][2] * scale, s3 = acc[i][3] * scale;
      float mloc = fmaxf(fmaxf(s0, s1), fmaxf(s2, s3));
#pragma unroll
      for (int off = 1; off < 16; off <<= 1)
        mloc = fmaxf(mloc, __shfl_xor_sync(0xffffffffu, mloc, off));
      float mnew = fmaxf(mprev[i], mloc);
      float p0 = __expf(s0 - mnew), p1 = __expf(s1 - mnew);
      float p2 = __expf(s2 - mnew), p3 = __expf(s3 - mnew);
      float ll = p0 + p1 + p2 + p3;
#pragma unroll
      for (int off = 1; off < 16; off <<= 1)
        ll += __shfl_xor_sync(0xffffffffu, ll, off);
      float alpha = __expf(mprev[i] - mnew);
      lsum[i] = lsum[i] * alpha + ll;
      mprev[i] = mnew;
#pragma unroll
      for (int n = 0; n < 8; n++) O[i][n] *= alpha;
      Ps[(tj * 4 + 0) * FL_SD + ti * 4 + i] = p0;
      Ps[(tj * 4 + 1) * FL_SD + ti * 4 + i] = p1;
      Ps[(tj * 4 + 2) * FL_SD + ti * 4 + i] = p2;
      Ps[(tj * 4 + 3) * FL_SD + ti * 4 + i] = p3;
    }
    __syncwarp();   // Ps row producers/consumers share a 16-lane group

    // PV: O[i][n] += P[i][jk] * V[jk][tj*8+n]
#pragma unroll 4
    for (int jk = 0; jk < 64; jk++) {
      float rp[4];
#pragma unroll
      for (int i = 0; i < 4; i++) rp[i] = Ps[jk * FL_SD + ti * 4 + i];
      float rv[8];
      *(float4*)(rv)     = *(const float4*)&Vs[jk * 128 + tj * 8];
      *(float4*)(rv + 4) = *(const float4*)&Vs[jk * 128 + tj * 8 + 4];
#pragma unroll
      for (int i = 0; i < 4; i++)
#pragma unroll
        for (int n = 0; n < 8; n++) O[i][n] += rp[i] * rv[n];
    }
  }

  // epilogue: normalize and store
#pragma unroll
  for (int i = 0; i < 4; i++) {
    float inv = 1.0f / lsum[i];
    size_t off = rowbase + (size_t)(q0 + ti * 4 + i) * HID + tj * 8;
    float4 o0 = make_float4(O[i][0] * inv, O[i][1] * inv, O[i][2] * inv, O[i][3] * inv);
    float4 o1 = make_float4(O[i][4] * inv, O[i][5] * inv, O[i][6] * inv, O[i][7] * inv);
    *(float4*)(o + off)     = o0;
    *(float4*)(o + off + 4) = o1;
  }
}

// ---------------------------------------------------------------------------
// SiLU(g1) * g3 elementwise
// ---------------------------------------------------------------------------
__global__ void __launch_bounds__(256) silumul_kernel(
    const float* __restrict__ a, const float* __restrict__ b,
    float* __restrict__ c) {
  int idx = blockIdx.x * 256 + threadIdx.x;
  float4 va = ((const float4*)a)[idx];
  float4 vb = ((const float4*)b)[idx];
  float4 vc;
  vc.x = va.x / (1.f + expf(-va.x)) * vb.x;
  vc.y = va.y / (1.f + expf(-va.y)) * vb.y;
  vc.z = va.z / (1.f + expf(-va.z)) * vb.z;
  vc.w = va.w / (1.f + expf(-va.w)) * vb.w;
  ((float4*)c)[idx] = vc;
}

// ---------------------------------------------------------------------------
// Launch
// ---------------------------------------------------------------------------
extern "C" void kernel_launch(void* const* d_in, const int* in_sizes, int n_in,
                              void* d_out, int out_size) {
  const float* hidden = (const float*)d_in[0];
  const float* Wq = (const float*)d_in[1];
  const float* Wk = (const float*)d_in[2];
  const float* Wv = (const float*)d_in[3];
  const float* Wo = (const float*)d_in[4];
  const float* w1 = (const float*)d_in[5];
  const float* w2 = (const float*)d_in[6];
  const float* w3 = (const float*)d_in[7];
  const float* ln1 = (const float*)d_in[8];
  const float* ln2 = (const float*)d_in[9];
  float* out = (float*)d_out;

  float *p_xn, *p_q, *p_k, *p_v, *p_ctx, *p_h, *p_yn, *p_g1, *p_g3, *p_t;
  cudaGetSymbolAddress((void**)&p_xn, g_xn);
  cudaGetSymbolAddress((void**)&p_q, g_q);
  cudaGetSymbolAddress((void**)&p_k, g_k);
  cudaGetSymbolAddress((void**)&p_v, g_v);
  cudaGetSymbolAddress((void**)&p_ctx, g_ctx);
  cudaGetSymbolAddress((void**)&p_h, g_h);
  cudaGetSymbolAddress((void**)&p_yn, g_yn);
  cudaGetSymbolAddress((void**)&p_g1, g_g1);
  cudaGetSymbolAddress((void**)&p_g3, g_g3);
  cudaGetSymbolAddress((void**)&p_t, g_t);

  static bool attr_set = false;
  if (!attr_set) {
    cudaFuncSetAttribute(flash_kernel, cudaFuncAttributeMaxDynamicSharedMemorySize,
                         FL_SMEM_FLOATS * sizeof(float));
    attr_set = true;
  }

  dim3 gemm_grid(GN / 128, MROWS / 128);   // (16, 32)

  // 1. RMSNorm 1
  rmsnorm_kernel<<<MROWS, 256>>>(hidden, ln1, p_xn);
  // RoPE table (cheap; recomputed per replay)
  rope_table_kernel<<<(SEQ * 64) / 256, 256>>>();
  // 2. Q/K/V projections
  sgemm_kernel<false><<<gemm_grid, 256>>>(p_xn, Wq, nullptr, p_q);
  sgemm_kernel<false><<<gemm_grid, 256>>>(p_xn, Wk, nullptr, p_k);
  sgemm_kernel<false><<<gemm_grid, 256>>>(p_xn, Wv, nullptr, p_v);
  // 3. RoPE on q, k
  rope_apply_kernel<<<(MROWS * NH * 64) / 256, 256>>>(p_q, p_k);
  // 4. Attention
  flash_kernel<<<dim3(SEQ / 64, BATCH * NH), 256, FL_SMEM_FLOATS * sizeof(float)>>>(
      p_q, p_k, p_v, p_ctx);
  // 5. Output projection + residual
  sgemm_kernel<true><<<gemm_grid, 256>>>(p_ctx, Wo, hidden, p_h);
  // 6. RMSNorm 2
  rmsnorm_kernel<<<MROWS, 256>>>(p_h, ln2, p_yn);
  // 7. MLP
  sgemm_kernel<false><<<gemm_grid, 256>>>(p_yn, w1, nullptr, p_g1);
  sgemm_kernel<false><<<gemm_grid, 256>>>(p_yn, w3, nullptr, p_g3);
  silumul_kernel<<<(MROWS * HID / 4) / 256, 256>>>(p_g1, p_g3, p_t);
  // 8. Down projection + residual -> output
  sgemm_kernel<true><<<gemm_grid, 256>>>(p_t, w2, p_h, out);
}

// round 3
// speedup vs baseline: 1.7027x; 1.7027x over previous
#include <cuda_runtime.h>
#include <cuda_bf16.h>
#include <math.h>
#include <stdint.h>

// ---------------------------------------------------------------------------
// Problem constants: B=2, S=2048, HID=2048, NH=16, HD=128, fp32 in/out.
// ---------------------------------------------------------------------------
#define BATCH 2
#define SEQ   2048
#define HID   2048
#define NH    16
#define HD    128
#define MROWS (BATCH * SEQ)          // 4096
#define EPS   1e-6f
#define N2    (HID * HID)

// ---------------------------------------------------------------------------
// Scratch (device globals; allocation inside kernel_launch is forbidden)
// ---------------------------------------------------------------------------
__device__ float g_xn [MROWS * HID];
__device__ float g_q  [MROWS * HID];
__device__ float g_k  [MROWS * HID];
__device__ float g_v  [MROWS * HID];
__device__ float g_ctx[MROWS * HID];
__device__ float g_h  [MROWS * HID];
__device__ float g_yn [MROWS * HID];
__device__ float g_g1 [MROWS * HID];
__device__ float g_g3 [MROWS * HID];
__device__ float g_t  [MROWS * HID];
__device__ float g_wt [7 * N2];      // transposed weights [N][K]
__device__ float g_cos[SEQ * (HD / 2)];
__device__ float g_sin[SEQ * (HD / 2)];

// ---------------------------------------------------------------------------
// mma.sync helpers (arch-portable tensor core path; tcgen05 rejected by the
// harness toolchain which targets plain sm_100)
// ---------------------------------------------------------------------------
__device__ __forceinline__ uint32_t smem_u32(const void* p) {
  uint32_t a;
  asm("{ .reg .u64 t; cvta.to.shared.u64 t, %1; cvt.u32.u64 %0, t; }"
      : "=r"(a) : "l"(p));
  return a;
}

__device__ __forceinline__ void ldsm_x4(uint32_t (&r)[4], uint32_t addr) {
  asm volatile("ldmatrix.sync.aligned.m8n8.x4.shared.b16 {%0,%1,%2,%3}, [%4];"
               : "=r"(r[0]), "=r"(r[1]), "=r"(r[2]), "=r"(r[3]) : "r"(addr));
}

__device__ __forceinline__ void mma16816(float (&d)[4], const uint32_t (&a)[4],
                                         const uint32_t b0, const uint32_t b1) {
  asm volatile(
      "mma.sync.aligned.m16n8k16.row.col.f32.bf16.bf16.f32 "
      "{%0,%1,%2,%3}, {%4,%5,%6,%7}, {%8,%9}, {%0,%1,%2,%3};"
      : "+f"(d[0]), "+f"(d[1]), "+f"(d[2]), "+f"(d[3])
      : "r"(a[0]), "r"(a[1]), "r"(a[2]), "r"(a[3]), "r"(b0), "r"(b1));
}

// fp32 -> bf16 hi + bf16 lo (residual) for a float4, packed as uint2 each.
__device__ __forceinline__ void split4(float4 v, uint2& hi, uint2& lo) {
  __nv_bfloat162 h0 = __floats2bfloat162_rn(v.x, v.y);
  __nv_bfloat162 h1 = __floats2bfloat162_rn(v.z, v.w);
  float2 f0 = __bfloat1622float2(h0);
  float2 f1 = __bfloat1622float2(h1);
  __nv_bfloat162 l0 = __floats2bfloat162_rn(v.x - f0.x, v.y - f0.y);
  __nv_bfloat162 l1 = __floats2bfloat162_rn(v.z - f1.x, v.w - f1.y);
  hi.x = *reinterpret_cast<uint32_t*>(&h0);
  hi.y = *reinterpret_cast<uint32_t*>(&h1);
  lo.x = *reinterpret_cast<uint32_t*>(&l0);
  lo.y = *reinterpret_cast<uint32_t*>(&l1);
}

// ---------------------------------------------------------------------------
// Tensor-core GEMM: C[M,N] = A[M,K] @ Wt[N,K]^T (+ D).
// CTA tile 128x128, KC=64, 8 warps (2M x 4N), warp tile 64x32.
// fp32 emulated as bf16 hi/lo -> 3 mma passes. Double-buffered smem.
// blockIdx.z selects among up to 3 (W, C) pairs sharing the same A.
// ---------------------------------------------------------------------------
#define BM 128
#define BN 128
#define KC 64
#define SA_BYTES 144                         // 64 bf16 (128B) + 16B pad
#define PLANE_BYTES (128 * SA_BYTES)         // 18432
#define STAGE_BYTES (4 * PLANE_BYTES)        // Ahi|Alo|Bhi|Blo = 73728
#define GEMM_SMEM (2 * STAGE_BYTES)          // 147456

template <bool ADD>
__global__ void __launch_bounds__(256) gemm_tc_kernel(
    const float* __restrict__ A,
    const float* __restrict__ Wt0, const float* __restrict__ Wt1,
    const float* __restrict__ Wt2,
    const float* __restrict__ Dres,
    float* __restrict__ C0, float* __restrict__ C1, float* __restrict__ C2) {
  const float* Wt = (blockIdx.z == 0) ? Wt0 : (blockIdx.z == 1 ? Wt1 : Wt2);
  float* C        = (blockIdx.z == 0) ? C0  : (blockIdx.z == 1 ? C1  : C2);

  extern __shared__ char sm[];
  uint32_t sbase = smem_u32(sm);

  int tid  = threadIdx.x;
  int lane = tid & 31;
  int wid  = tid >> 5;
  int wm   = wid & 1;       // 0..1  -> M offset 64*wm
  int wn   = wid >> 1;      // 0..3  -> N offset 32*wn
  int m0 = blockIdx.y * BM;
  int n0 = blockIdx.x * BN;

  const float4* Ag = (const float4*)(A  + (size_t)m0 * HID);
  const float4* Bg = (const float4*)(Wt + (size_t)n0 * HID);

  float acc[4][4][4];
#pragma unroll
  for (int i = 0; i < 4; i++)
#pragma unroll
    for (int j = 0; j < 4; j++)
#pragma unroll
      for (int q = 0; q < 4; q++) acc[i][j][q] = 0.f;

  // staging lambda-ish macro: copy chunk c into stage s
#define STAGE_CHUNK(s, c) do {                                                \
    int kc4 = (c) * (KC / 4);                                                 \
    char* ahi = sm + (s) * STAGE_BYTES;                                       \
    char* alo = ahi + PLANE_BYTES;                                            \
    char* bhi = ahi + 2 * PLANE_BYTES;                                        \
    char* blo = ahi + 3 * PLANE_BYTES;                                        \
    _Pragma("unroll")                                                         \
    for (int it = 0; it < 8; ++it) {                                          \
      int idx = it * 256 + tid;                                               \
      int r = idx >> 4, k4 = idx & 15;                                        \
      float4 v = Ag[(size_t)r * (HID / 4) + kc4 + k4];                        \
      uint2 h, l; split4(v, h, l);                                            \
      int off = r * SA_BYTES + k4 * 8;                                        \
      *(uint2*)(ahi + off) = h;                                               \
      *(uint2*)(alo + off) = l;                                               \
    }                                                                         \
    _Pragma("unroll")                                                         \
    for (int it = 0; it < 8; ++it) {                                          \
      int idx = it * 256 + tid;                                               \
      int r = idx >> 4, k4 = idx & 15;                                        \
      float4 v = Bg[(size_t)r * (HID / 4) + kc4 + k4];                        \
      uint2 h, l; split4(v, h, l);                                            \
      int off = r * SA_BYTES + k4 * 8;                                        \
      *(uint2*)(bhi + off) = h;                                               \
      *(uint2*)(blo + off) = l;                                               \
    }                                                                         \
  } while (0)

  // ldmatrix per-lane address offsets (bytes within a plane)
  // A: row = wm*64 + mi*16 + (lane & 15), col(k-elems) = ks*16 + ((lane>>4)<<3)
  int a_row = wm * 64 + (lane & 15);
  int a_col8 = (lane >> 4) << 3;
  // B: row = wn*32 + nj*16 + ((lane>>4)<<3) + (lane&7),
  //    col = ks*16 + (((lane>>3)&1)<<3)
  int b_row = wn * 32 + ((lane >> 4) << 3) + (lane & 7);
  int b_col8 = ((lane >> 3) & 1) << 3;

  STAGE_CHUNK(0, 0);
  __syncthreads();

  const int NCHUNK = HID / KC;   // 32
  int stage = 0;

  for (int c = 0; c < NCHUNK; ++c) {
    if (c + 1 < NCHUNK) STAGE_CHUNK(stage ^ 1, c + 1);

    uint32_t pAhi = sbase + stage * STAGE_BYTES;
    uint32_t pAlo = pAhi + PLANE_BYTES;
    uint32_t pBhi = pAhi + 2 * PLANE_BYTES;
    uint32_t pBlo = pAhi + 3 * PLANE_BYTES;

#pragma unroll
    for (int ks = 0; ks < 4; ++ks) {
      int kbase = ks * 16;
      uint32_t ahi[4][4], alo[4][4];
#pragma unroll
      for (int mi = 0; mi < 4; ++mi) {
        uint32_t off = (uint32_t)((a_row + mi * 16) * SA_BYTES +
                                  (kbase + a_col8) * 2);
        ldsm_x4(ahi[mi], pAhi + off);
        ldsm_x4(alo[mi], pAlo + off);
      }
      uint32_t bhi[4][2], blo[4][2];
#pragma unroll
      for (int nj = 0; nj < 2; ++nj) {
        uint32_t off = (uint32_t)((b_row + nj * 16) * SA_BYTES +
                                  (kbase + b_col8) * 2);
        uint32_t rh[4], rl[4];
        ldsm_x4(rh, pBhi + off);
        ldsm_x4(rl, pBlo + off);
        bhi[nj * 2 + 0][0] = rh[0]; bhi[nj * 2 + 0][1] = rh[1];
        bhi[nj * 2 + 1][0] = rh[2]; bhi[nj * 2 + 1][1] = rh[3];
        blo[nj * 2 + 0][0] = rl[0]; blo[nj * 2 + 0][1] = rl[1];
        blo[nj * 2 + 1][0] = rl[2]; blo[nj * 2 + 1][1] = rl[3];
      }
#pragma unroll
      for (int mi = 0; mi < 4; ++mi)
#pragma unroll
        for (int nt = 0; nt < 4; ++nt) {
          mma16816(acc[mi][nt], ahi[mi], bhi[nt][0], bhi[nt][1]);
          mma16816(acc[mi][nt], ahi[mi], blo[nt][0], blo[nt][1]);
          mma16816(acc[mi][nt], alo[mi], bhi[nt][0], bhi[nt][1]);
        }
    }
    __syncthreads();
    stage ^= 1;
  }
#undef STAGE_CHUNK

  // Epilogue: c0,c1 -> (row, col..col+1); c2,c3 -> (row+8, ...)
  int er = m0 + wm * 64 + (lane >> 2);
  int ec = n0 + wn * 32 + (lane & 3) * 2;
#pragma unroll
  for (int mi = 0; mi < 4; ++mi) {
#pragma unroll
    for (int nt = 0; nt < 4; ++nt) {
      size_t o0 = (size_t)(er + mi * 16) * HID + ec + nt * 8;
      size_t o1 = o0 + 8 * HID;
      float2 v0 = make_float2(acc[mi][nt][0], acc[mi][nt][1]);
      float2 v1 = make_float2(acc[mi][nt][2], acc[mi][nt][3]);
      if (ADD) {
        float2 d0 = *(const float2*)(Dres + o0);
        float2 d1 = *(const float2*)(Dres + o1);
        v0.x += d0.x; v0.y += d0.y;
        v1.x += d1.x; v1.y += d1.y;
      }
      *(float2*)(C + o0) = v0;
      *(float2*)(C + o1) = v1;
    }
  }
}

// ---------------------------------------------------------------------------
// Tiled transpose: Wt[n][k] = W[k][n], 2048x2048.
// ---------------------------------------------------------------------------
__global__ void __launch_bounds__(256) transpose_kernel(
    const float* __restrict__ in, float* __restrict__ out) {
  __shared__ float t[32][33];
  int tx = threadIdx.x, ty = threadIdx.y;
  int x = blockIdx.x * 32 + tx;
  int y0 = blockIdx.y * 32;
#pragma unroll
  for (int i = ty; i < 32; i += 8)
    t[i][tx] = in[(size_t)(y0 + i) * HID + x];
  __syncthreads();
  int ox = y0 + tx;
  int oy0 = blockIdx.x * 32;
#pragma unroll
  for (int i = ty; i < 32; i += 8)
    out[(size_t)(oy0 + i) * HID + ox] = t[tx][i];
}

// ---------------------------------------------------------------------------
// RMSNorm: one block per row (2048 elems), fp32.
// ---------------------------------------------------------------------------
__global__ void __launch_bounds__(256) rmsnorm_kernel(
    const float* __restrict__ x, const float* __restrict__ w,
    float* __restrict__ y) {
  int row = blockIdx.x;
  const float4* x4 = (const float4*)(x + (size_t)row * HID);
  const float4* w4 = (const float4*)w;
  float4*       y4 = (float4*)(y + (size_t)row * HID);
  int tid = threadIdx.x;

  float s = 0.f;
#pragma unroll
  for (int i = tid; i < HID / 4; i += 256) {
    float4 v = x4[i];
    s += v.x * v.x + v.y * v.y + v.z * v.z + v.w * v.w;
  }
#pragma unroll
  for (int off = 16; off > 0; off >>= 1)
    s += __shfl_xor_sync(0xffffffffu, s, off);

  __shared__ float red[8];
  __shared__ float s_inv;
  if ((tid & 31) == 0) red[tid >> 5] = s;
  __syncthreads();
  if (tid == 0) {
    float t = 0.f;
#pragma unroll
    for (int i = 0; i < 8; i++) t += red[i];
    s_inv = rsqrtf(t / (float)HID + EPS);
  }
  __syncthreads();
  float inv = s_inv;

#pragma unroll
  for (int i = tid; i < HID / 4; i += 256) {
    float4 v = x4[i];
    float4 ww = w4[i];
    float4 o;
    o.x = v.x * inv * ww.x;
    o.y = v.y * inv * ww.y;
    o.z = v.z * inv * ww.z;
    o.w = v.w * inv * ww.w;
    y4[i] = o;
  }
}

// ---------------------------------------------------------------------------
// RoPE table + apply
// ---------------------------------------------------------------------------
__global__ void rope_table_kernel() {
  int idx = blockIdx.x * 256 + threadIdx.x;
  int s = idx >> 6;
  int d = idx & 63;
  float invf = 1.0f / powf(10000.0f, (float)d / 64.0f);
  float ang = (float)s * invf;
  g_cos[idx] = cosf(ang);
  g_sin[idx] = sinf(ang);
}

__global__ void __launch_bounds__(256) rope_apply_kernel(
    float* __restrict__ q, float* __restrict__ k) {
  int idx = blockIdx.x * 256 + threadIdx.x;
  int d = idx & 63;
  int h = (idx >> 6) & 15;
  int row = idx >> 10;
  int s = row & (SEQ - 1);

  float c  = g_cos[s * 64 + d];
  float sn = g_sin[s * 64 + d];
  size_t base = (size_t)row * HID + h * HD + d;

  float q1 = q[base], q2 = q[base + 64];
  q[base]      = q1 * c - q2 * sn;
  q[base + 64] = q2 * c + q1 * sn;

  float k1 = k[base], k2 = k[base + 64];
  k[base]      = k1 * c - k2 * sn;
  k[base + 64] = k2 * c + k1 * sn;
}

// ---------------------------------------------------------------------------
// Flash attention (non-causal, fp32). BM=BN=64, HD=128, 256 threads.
// ---------------------------------------------------------------------------
#define FL_SD 65
#define FL_SMEM_FLOATS (128 * FL_SD * 2 + 64 * 128 + 64 * FL_SD)

__global__ void __launch_bounds__(256) flash_kernel(
    const float* __restrict__ q, const float* __restrict__ k,
    const float* __restrict__ v, float* __restrict__ o) {
  extern __shared__ float smf[];
  float* Qs = smf;
  float* Ks = Qs + 128 * FL_SD;
  float* Vs = Ks + 128 * FL_SD;
  float* Ps = Vs + 64 * 128;

  int qb = blockIdx.x;
  int bh = blockIdx.y;
  int b = bh >> 4, h = bh & 15;
  int tid = threadIdx.x;
  int ti = tid >> 4;
  int tj = tid & 15;

  size_t rowbase = (size_t)b * SEQ * HID + (size_t)h * HD;
  int q0 = qb * 64;

#pragma unroll
  for (int it = 0; it < 8; it++) {
    int e = it * 1024 + tid * 4;
    int r = e >> 7, c = e & 127;
    float4 val = *(const float4*)(q + rowbase + (size_t)(q0 + r) * HID + c);
    Qs[(c + 0) * FL_SD + r] = val.x;
    Qs[(c + 1) * FL_SD + r] = val.y;
    Qs[(c + 2) * FL_SD + r] = val.z;
    Qs[(c + 3) * FL_SD + r] = val.w;
  }

  float O[4][8];
  float mprev[4], lsum[4];
#pragma unroll
  for (int i = 0; i < 4; i++) {
    mprev[i] = -INFINITY;
    lsum[i] = 0.f;
#pragma unroll
    for (int n = 0; n < 8; n++) O[i][n] = 0.f;
  }
  const float scale = 0.08838834764831845f;

  for (int nb = 0; nb < SEQ / 64; nb++) {
    int k0 = nb * 64;
    __syncthreads();
#pragma unroll
    for (int it = 0; it < 8; it++) {
      int e = it * 1024 + tid * 4;
      int r = e >> 7, c = e & 127;
      float4 kv = *(const float4*)(k + rowbase + (size_t)(k0 + r) * HID + c);
      Ks[(c + 0) * FL_SD + r] = kv.x;
      Ks[(c + 1) * FL_SD + r] = kv.y;
      Ks[(c + 2) * FL_SD + r] = kv.z;
      Ks[(c + 3) * FL_SD + r] = kv.w;
      float4 vv = *(const float4*)(v + rowbase + (size_t)(k0 + r) * HID + c);
      *(float4*)&Vs[r * 128 + c] = vv;
    }
    __syncthreads();

    float acc[4][4];
#pragma unroll
    for (int i = 0; i < 4; i++)
#pragma unroll
      for (int j = 0; j < 4; j++) acc[i][j] = 0.f;

#pragma unroll 8
    for (int kk = 0; kk < 128; kk++) {
      float ra[4], rb[4];
#pragma unroll
      for (int i = 0; i < 4; i++) ra[i] = Qs[kk * FL_SD + ti * 4 + i];
#pragma unroll
      for (int j = 0; j < 4; j++) rb[j] = Ks[kk * FL_SD + tj * 4 + j];
#pragma unroll
      for (int i = 0; i < 4; i++)
#pragma unroll
        for (int j = 0; j < 4; j++) acc[i][j] += ra[i] * rb[j];
    }

#pragma unroll
    for (int i = 0; i < 4; i++) {
      float s0 = acc[i][0] * scale, s1 = acc[i][1] * scale;
      float s2 = acc[i][2] * scale, s3 = acc[i][3] * scale;
      float mloc = fmaxf(fmaxf(s0, s1), fmaxf(s2, s3));
#pragma unroll
      for (int off = 1; off < 16; off <<= 1)
        mloc = fmaxf(mloc, __shfl_xor_sync(0xffffffffu, mloc, off));
      float mnew = fmaxf(mprev[i], mloc);
      float p0 = __expf(s0 - mnew), p1 = __expf(s1 - mnew);
      float p2 = __expf(s2 - mnew), p3 = __expf(s3 - mnew);
      float ll = p0 + p1 + p2 + p3;
#pragma unroll
      for (int off = 1; off < 16; off <<= 1)
        ll += __shfl_xor_sync(0xffffffffu, ll, off);
      float alpha = __expf(mprev[i] - mnew);
      lsum[i] = lsum[i] * alpha + ll;
      mprev[i] = mnew;
#pragma unroll
      for (int n = 0; n < 8; n++) O[i][n] *= alpha;
      Ps[(tj * 4 + 0) * FL_SD + ti * 4 + i] = p0;
      Ps[(tj * 4 + 1) * FL_SD + ti * 4 + i] = p1;
      Ps[(tj * 4 + 2) * FL_SD + ti * 4 + i] = p2;
      Ps[(tj * 4 + 3) * FL_SD + ti * 4 + i] = p3;
    }
    __syncwarp();

#pragma unroll 4
    for (int jk = 0; jk < 64; jk++) {
      float rp[4];
#pragma unroll
      for (int i = 0; i < 4; i++) rp[i] = Ps[jk * FL_SD + ti * 4 + i];
      float rv[8];
      *(float4*)(rv)     = *(const float4*)&Vs[jk * 128 + tj * 8];
      *(float4*)(rv + 4) = *(const float4*)&Vs[jk * 128 + tj * 8 + 4];
#pragma unroll
      for (int i = 0; i < 4; i++)
#pragma unroll
        for (int n = 0; n < 8; n++) O[i][n] += rp[i] * rv[n];
    }
  }

#pragma unroll
  for (int i = 0; i < 4; i++) {
    float inv = 1.0f / lsum[i];
    size_t off = rowbase + (size_t)(q0 + ti * 4 + i) * HID + tj * 8;
    float4 o0 = make_float4(O[i][0] * inv, O[i][1] * inv, O[i][2] * inv, O[i][3] * inv);
    float4 o1 = make_float4(O[i][4] * inv, O[i][5] * inv, O[i][6] * inv, O[i][7] * inv);
    *(float4*)(o + off)     = o0;
    *(float4*)(o + off + 4) = o1;
  }
}

// ---------------------------------------------------------------------------
// SiLU(g1) * g3 elementwise
// ---------------------------------------------------------------------------
__global__ void __launch_bounds__(256) silumul_kernel(
    const float* __restrict__ a, const float* __restrict__ b,
    float* __restrict__ c) {
  int idx = blockIdx.x * 256 + threadIdx.x;
  float4 va = ((const float4*)a)[idx];
  float4 vb = ((const float4*)b)[idx];
  float4 vc;
  vc.x = va.x / (1.f + expf(-va.x)) * vb.x;
  vc.y = va.y / (1.f + expf(-va.y)) * vb.y;
  vc.z = va.z / (1.f + expf(-va.z)) * vb.z;
  vc.w = va.w / (1.f + expf(-va.w)) * vb.w;
  ((float4*)c)[idx] = vc;
}

// ---------------------------------------------------------------------------
// Launch
// ---------------------------------------------------------------------------
extern "C" void kernel_launch(void* const* d_in, const int* in_sizes, int n_in,
                              void* d_out, int out_size) {
  const float* hidden = (const float*)d_in[0];
  const float* Wq = (const float*)d_in[1];
  const float* Wk = (const float*)d_in[2];
  const float* Wv = (const float*)d_in[3];
  const float* Wo = (const float*)d_in[4];
  const float* w1 = (const float*)d_in[5];
  const float* w2 = (const float*)d_in[6];
  const float* w3 = (const float*)d_in[7];
  const float* ln1 = (const float*)d_in[8];
  const float* ln2 = (const float*)d_in[9];
  float* out = (float*)d_out;

  float *p_xn, *p_q, *p_k, *p_v, *p_ctx, *p_h, *p_yn, *p_g1, *p_g3, *p_t, *p_wt;
  cudaGetSymbolAddress((void**)&p_xn, g_xn);
  cudaGetSymbolAddress((void**)&p_q, g_q);
  cudaGetSymbolAddress((void**)&p_k, g_k);
  cudaGetSymbolAddress((void**)&p_v, g_v);
  cudaGetSymbolAddress((void**)&p_ctx, g_ctx);
  cudaGetSymbolAddress((void**)&p_h, g_h);
  cudaGetSymbolAddress((void**)&p_yn, g_yn);
  cudaGetSymbolAddress((void**)&p_g1, g_g1);
  cudaGetSymbolAddress((void**)&p_g3, g_g3);
  cudaGetSymbolAddress((void**)&p_t, g_t);
  cudaGetSymbolAddress((void**)&p_wt, g_wt);

  static bool attr_set = false;
  if (!attr_set) {
    cudaFuncSetAttribute(flash_kernel, cudaFuncAttributeMaxDynamicSharedMemorySize,
                         FL_SMEM_FLOATS * sizeof(float));
    cudaFuncSetAttribute(gemm_tc_kernel<false>,
                         cudaFuncAttributeMaxDynamicSharedMemorySize, GEMM_SMEM);
    cudaFuncSetAttribute(gemm_tc_kernel<true>,
                         cudaFuncAttributeMaxDynamicSharedMemorySize, GEMM_SMEM);
    attr_set = true;
  }

  float* wtq = p_wt + 0ull * N2;
  float* wtk = p_wt + 1ull * N2;
  float* wtv = p_wt + 2ull * N2;
  float* wto = p_wt + 3ull * N2;
  float* wt1 = p_wt + 4ull * N2;
  float* wt3 = p_wt + 5ull * N2;
  float* wt2 = p_wt + 6ull * N2;

  dim3 tgrid(64, 64);
  dim3 tblk(32, 8);
  transpose_kernel<<<tgrid, tblk>>>(Wq, wtq);
  transpose_kernel<<<tgrid, tblk>>>(Wk, wtk);
  transpose_kernel<<<tgrid, tblk>>>(Wv, wtv);
  transpose_kernel<<<tgrid, tblk>>>(Wo, wto);
  transpose_kernel<<<tgrid, tblk>>>(w1, wt1);
  transpose_kernel<<<tgrid, tblk>>>(w3, wt3);
  transpose_kernel<<<tgrid, tblk>>>(w2, wt2);

  // 1. RMSNorm 1 + RoPE table
  rmsnorm_kernel<<<MROWS, 256>>>(hidden, ln1, p_xn);
  rope_table_kernel<<<(SEQ * 64) / 256, 256>>>();

  // 2. Q/K/V projections (one fused launch, z=3)
  dim3 qkv_grid(HID / BN, MROWS / BM, 3);
  gemm_tc_kernel<false><<<qkv_grid, 256, GEMM_SMEM>>>(
      p_xn, wtq, wtk, wtv, nullptr, p_q, p_k, p_v);

  // 3. RoPE on q, k
  rope_apply_kernel<<<(MROWS * NH * 64) / 256, 256>>>(p_q, p_k);

  // 4. Attention
  flash_kernel<<<dim3(SEQ / 64, BATCH * NH), 256, FL_SMEM_FLOATS * sizeof(float)>>>(
      p_q, p_k, p_v, p_ctx);

  // 5. Output projection + residual
  dim3 g1_grid(HID / BN, MROWS / BM, 1);
  gemm_tc_kernel<true><<<g1_grid, 256, GEMM_SMEM>>>(
      p_ctx, wto, nullptr, nullptr, hidden, p_h, nullptr, nullptr);

  // 6. RMSNorm 2
  rmsnorm_kernel<<<MROWS, 256>>>(p_h, ln2, p_yn);

  // 7. MLP up+gate (one fused launch, z=2)
  dim3 g2_grid(HID / BN, MROWS / BM, 2);
  gemm_tc_kernel<false><<<g2_grid, 256, GEMM_SMEM>>>(
      p_yn, wt1, wt3, nullptr, nullptr, p_g1, p_g3, nullptr);

  silumul_kernel<<<(MROWS * HID / 4) / 256, 256>>>(p_g1, p_g3, p_t);

  // 8. Down projection + residual -> output
  gemm_tc_kernel<true><<<g1_grid, 256, GEMM_SMEM>>>(
      p_t, wt2, nullptr, nullptr, p_h, out, nullptr, nullptr);
}

// round 4
// speedup vs baseline: 2.9304x; 1.7210x over previous
#include <cuda_runtime.h>
#include <cuda_bf16.h>
#include <math.h>
#include <stdint.h>

// ---------------------------------------------------------------------------
// Problem constants: B=2, S=2048, HID=2048, NH=16, HD=128, fp32 in/out.
// ---------------------------------------------------------------------------
#define BATCH 2
#define SEQ   2048
#define HID   2048
#define NH    16
#define HD    128
#define MROWS (BATCH * SEQ)          // 4096
#define EPS   1e-6f
#define N2    (HID * HID)

// ---------------------------------------------------------------------------
// Scratch (device globals)
// ---------------------------------------------------------------------------
__device__ float g_qf [MROWS * HID];
__device__ float g_kf [MROWS * HID];
__device__ float g_vf [MROWS * HID];
__device__ float g_h  [MROWS * HID];
__device__ float g_g1 [MROWS * HID];
__device__ float g_g3 [MROWS * HID];
// bf16 hi/lo planes
__device__ __nv_bfloat16 g_xnh[MROWS * HID], g_xnl[MROWS * HID];
__device__ __nv_bfloat16 g_qh [MROWS * HID], g_ql [MROWS * HID];
__device__ __nv_bfloat16 g_kh [MROWS * HID], g_kl [MROWS * HID];
__device__ __nv_bfloat16 g_vb [MROWS * HID];
__device__ __nv_bfloat16 g_ch [MROWS * HID], g_cl [MROWS * HID];
__device__ __nv_bfloat16 g_ynh[MROWS * HID], g_ynl[MROWS * HID];
__device__ __nv_bfloat16 g_th [MROWS * HID], g_tl [MROWS * HID];
__device__ __nv_bfloat16 g_wth[7 * N2], g_wtl[7 * N2];   // [N][K] planes
__device__ float g_cos[SEQ * (HD / 2)];
__device__ float g_sin[SEQ * (HD / 2)];

// ---------------------------------------------------------------------------
// mma.sync helpers
// ---------------------------------------------------------------------------
__device__ __forceinline__ uint32_t smem_u32(const void* p) {
  uint32_t a;
  asm("{ .reg .u64 t; cvta.to.shared.u64 t, %1; cvt.u32.u64 %0, t; }"
      : "=r"(a) : "l"(p));
  return a;
}
__device__ __forceinline__ void ldsm_x4(uint32_t (&r)[4], uint32_t addr) {
  asm volatile("ldmatrix.sync.aligned.m8n8.x4.shared.b16 {%0,%1,%2,%3}, [%4];"
               : "=r"(r[0]), "=r"(r[1]), "=r"(r[2]), "=r"(r[3]) : "r"(addr));
}
__device__ __forceinline__ void ldsm_x4_t(uint32_t (&r)[4], uint32_t addr) {
  asm volatile("ldmatrix.sync.aligned.m8n8.x4.trans.shared.b16 {%0,%1,%2,%3}, [%4];"
               : "=r"(r[0]), "=r"(r[1]), "=r"(r[2]), "=r"(r[3]) : "r"(addr));
}
__device__ __forceinline__ void mma16816(float (&d)[4], const uint32_t (&a)[4],
                                         const uint32_t b0, const uint32_t b1) {
  asm volatile(
      "mma.sync.aligned.m16n8k16.row.col.f32.bf16.bf16.f32 "
      "{%0,%1,%2,%3}, {%4,%5,%6,%7}, {%8,%9}, {%0,%1,%2,%3};"
      : "+f"(d[0]), "+f"(d[1]), "+f"(d[2]), "+f"(d[3])
      : "r"(a[0]), "r"(a[1]), "r"(a[2]), "r"(a[3]), "r"(b0), "r"(b1));
}

__device__ __forceinline__ uint32_t packbf(float a, float b) {
  __nv_bfloat162 p = __floats2bfloat162_rn(a, b);
  return *reinterpret_cast<uint32_t*>(&p);
}
// fp32 -> (hi, lo) bf16
__device__ __forceinline__ void split1(float x, __nv_bfloat16& h, __nv_bfloat16& l) {
  h = __float2bfloat16_rn(x);
  l = __float2bfloat16_rn(x - __bfloat162float(h));
}
__device__ __forceinline__ void split4(float4 v, uint2& hi, uint2& lo) {
  __nv_bfloat162 h0 = __floats2bfloat162_rn(v.x, v.y);
  __nv_bfloat162 h1 = __floats2bfloat162_rn(v.z, v.w);
  float2 f0 = __bfloat1622float2(h0);
  float2 f1 = __bfloat1622float2(h1);
  __nv_bfloat162 l0 = __floats2bfloat162_rn(v.x - f0.x, v.y - f0.y);
  __nv_bfloat162 l1 = __floats2bfloat162_rn(v.z - f1.x, v.w - f1.y);
  hi.x = *reinterpret_cast<uint32_t*>(&h0);
  hi.y = *reinterpret_cast<uint32_t*>(&h1);
  lo.x = *reinterpret_cast<uint32_t*>(&l0);
  lo.y = *reinterpret_cast<uint32_t*>(&l1);
}

// ---------------------------------------------------------------------------
// GEMM: C[M,N] = A @ B^T (+D). A,B given as bf16 hi/lo K-major planes.
// CTA 128x128, KC=64, 8 warps (2Mx4N), warp tile 64x32, 3-pass hi/lo.
// ---------------------------------------------------------------------------
#define BM 128
#define BN 128
#define KC 64
#define SA_BYTES 144
#define PLANE_BYTES (128 * SA_BYTES)
#define STAGE_BYTES (4 * PLANE_BYTES)
#define GEMM_SMEM (2 * STAGE_BYTES)

template <bool ADD>
__global__ void __launch_bounds__(256) gemm_tc_kernel(
    const __nv_bfloat16* __restrict__ Ah, const __nv_bfloat16* __restrict__ Al,
    const __nv_bfloat16* __restrict__ Bh0, const __nv_bfloat16* __restrict__ Bl0,
    const __nv_bfloat16* __restrict__ Bh1, const __nv_bfloat16* __restrict__ Bl1,
    const __nv_bfloat16* __restrict__ Bh2, const __nv_bfloat16* __restrict__ Bl2,
    const float* __restrict__ Dres,
    float* __restrict__ C0, float* __restrict__ C1, float* __restrict__ C2) {
  const __nv_bfloat16* Bh = (blockIdx.z == 0) ? Bh0 : (blockIdx.z == 1 ? Bh1 : Bh2);
  const __nv_bfloat16* Bl = (blockIdx.z == 0) ? Bl0 : (blockIdx.z == 1 ? Bl1 : Bl2);
  float* C = (blockIdx.z == 0) ? C0 : (blockIdx.z == 1 ? C1 : C2);

  extern __shared__ char sm[];
  uint32_t sbase = smem_u32(sm);

  int tid  = threadIdx.x;
  int lane = tid & 31;
  int wid  = tid >> 5;
  int wm   = wid & 1;
  int wn   = wid >> 1;
  int m0 = blockIdx.y * BM;
  int n0 = blockIdx.x * BN;

  const __nv_bfloat16* Agh = Ah + (size_t)m0 * HID;
  const __nv_bfloat16* Agl = Al + (size_t)m0 * HID;
  const __nv_bfloat16* Bgh = Bh + (size_t)n0 * HID;
  const __nv_bfloat16* Bgl = Bl + (size_t)n0 * HID;

  float acc[4][4][4];
#pragma unroll
  for (int i = 0; i < 4; i++)
#pragma unroll
    for (int j = 0; j < 4; j++)
#pragma unroll
      for (int q = 0; q < 4; q++) acc[i][j][q] = 0.f;

#define CPY_PLANE(dst, src, kc) do {                                          \
    _Pragma("unroll")                                                         \
    for (int it = 0; it < 4; ++it) {                                          \
      int idx = it * 256 + tid;                                               \
      int r = idx >> 3, cc = idx & 7;                                         \
      *(uint4*)((dst) + r * SA_BYTES + cc * 16) =                             \
          *(const uint4*)((src) + (size_t)r * HID + (kc) + cc * 8);           \
    }                                                                         \
  } while (0)

#define STAGE_CHUNK(s, c) do {                                                \
    char* base = sm + (s) * STAGE_BYTES;                                      \
    int kc = (c) * KC;                                                        \
    CPY_PLANE(base,                   Agh, kc);                               \
    CPY_PLANE(base + PLANE_BYTES,     Agl, kc);                               \
    CPY_PLANE(base + 2 * PLANE_BYTES, Bgh, kc);                               \
    CPY_PLANE(base + 3 * PLANE_BYTES, Bgl, kc);                               \
  } while (0)

  int a_row = wm * 64 + (lane & 15);
  int a_col8 = (lane >> 4) << 3;
  int b_row = wn * 32 + ((lane >> 4) << 3) + (lane & 7);
  int b_col8 = ((lane >> 3) & 1) << 3;

  STAGE_CHUNK(0, 0);
  __syncthreads();

  const int NCHUNK = HID / KC;
  int stage = 0;

  for (int c = 0; c < NCHUNK; ++c) {
    if (c + 1 < NCHUNK) STAGE_CHUNK(stage ^ 1, c + 1);

    uint32_t pAhi = sbase + stage * STAGE_BYTES;
    uint32_t pAlo = pAhi + PLANE_BYTES;
    uint32_t pBhi = pAhi + 2 * PLANE_BYTES;
    uint32_t pBlo = pAhi + 3 * PLANE_BYTES;

#pragma unroll
    for (int ks = 0; ks < 4; ++ks) {
      int kbase = ks * 16;
      uint32_t ahi[4][4], alo[4][4];
#pragma unroll
      for (int mi = 0; mi < 4; ++mi) {
        uint32_t off = (uint32_t)((a_row + mi * 16) * SA_BYTES +
                                  (kbase + a_col8) * 2);
        ldsm_x4(ahi[mi], pAhi + off);
        ldsm_x4(alo[mi], pAlo + off);
      }
      uint32_t bhi[4][2], blo[4][2];
#pragma unroll
      for (int nj = 0; nj < 2; ++nj) {
        uint32_t off = (uint32_t)((b_row + nj * 16) * SA_BYTES +
                                  (kbase + b_col8) * 2);
        uint32_t rh[4], rl[4];
        ldsm_x4(rh, pBhi + off);
        ldsm_x4(rl, pBlo + off);
        bhi[nj * 2 + 0][0] = rh[0]; bhi[nj * 2 + 0][1] = rh[1];
        bhi[nj * 2 + 1][0] = rh[2]; bhi[nj * 2 + 1][1] = rh[3];
        blo[nj * 2 + 0][0] = rl[0]; blo[nj * 2 + 0][1] = rl[1];
        blo[nj * 2 + 1][0] = rl[2]; blo[nj * 2 + 1][1] = rl[3];
      }
#pragma unroll
      for (int mi = 0; mi < 4; ++mi)
#pragma unroll
        for (int nt = 0; nt < 4; ++nt) {
          mma16816(acc[mi][nt], ahi[mi], bhi[nt][0], bhi[nt][1]);
          mma16816(acc[mi][nt], ahi[mi], blo[nt][0], blo[nt][1]);
          mma16816(acc[mi][nt], alo[mi], bhi[nt][0], bhi[nt][1]);
        }
    }
    __syncthreads();
    stage ^= 1;
  }
#undef STAGE_CHUNK
#undef CPY_PLANE

  int er = m0 + wm * 64 + (lane >> 2);
  int ec = n0 + wn * 32 + (lane & 3) * 2;
#pragma unroll
  for (int mi = 0; mi < 4; ++mi) {
#pragma unroll
    for (int nt = 0; nt < 4; ++nt) {
      size_t o0 = (size_t)(er + mi * 16) * HID + ec + nt * 8;
      size_t o1 = o0 + 8 * HID;
      float2 v0 = make_float2(acc[mi][nt][0], acc[mi][nt][1]);
      float2 v1 = make_float2(acc[mi][nt][2], acc[mi][nt][3]);
      if (ADD) {
        float2 d0 = *(const float2*)(Dres + o0);
        float2 d1 = *(const float2*)(Dres + o1);
        v0.x += d0.x; v0.y += d0.y;
        v1.x += d1.x; v1.y += d1.y;
      }
      *(float2*)(C + o0) = v0;
      *(float2*)(C + o1) = v1;
    }
  }
}

// ---------------------------------------------------------------------------
// Flash attention with mma.sync. 64 q-rows/CTA, 4 warps, BN=64, HD=128.
// QK: hi/lo 3-pass bf16; PV: single bf16 (P in [0,1], V bf16).
// ---------------------------------------------------------------------------
#define FA_ST 136                    // bf16 elems per smem row (128 + 8 pad)
#define FA_SMEM (3 * 64 * FA_ST * 2) // Kh | Kl | V  = 52224 bytes

__global__ void __launch_bounds__(128) flash_mma_kernel(
    const __nv_bfloat16* __restrict__ qh, const __nv_bfloat16* __restrict__ ql,
    const __nv_bfloat16* __restrict__ kh, const __nv_bfloat16* __restrict__ kl,
    const __nv_bfloat16* __restrict__ vb,
    __nv_bfloat16* __restrict__ ctxh, __nv_bfloat16* __restrict__ ctxl) {
  extern __shared__ char smc[];
  __nv_bfloat16* sKh = (__nv_bfloat16*)smc;
  __nv_bfloat16* sKl = sKh + 64 * FA_ST;
  __nv_bfloat16* sV  = sKl + 64 * FA_ST;
  uint32_t pKh = smem_u32(sKh);
  uint32_t pKl = smem_u32(sKl);
  uint32_t pV  = smem_u32(sV);

  int qb = blockIdx.x;
  int bh = blockIdx.y;
  int b = bh >> 4, h = bh & 15;
  int tid = threadIdx.x;
  int lane = tid & 31;
  int w = tid >> 5;
  int colbase = h * HD;
  size_t row0 = (size_t)b * SEQ + qb * 64;   // global row of q-tile row 0

  // ---- load Q fragments (hi then lo), staged through sKh ----
  uint32_t qfh[8][4], qfl[8][4];
  uint32_t qaddr = pKh + (uint32_t)(((w * 16 + (lane & 15)) * FA_ST +
                                     ((lane >> 4) << 3)) * 2);
#pragma unroll
  for (int pass = 0; pass < 2; ++pass) {
    const __nv_bfloat16* src = pass ? ql : qh;
#pragma unroll
    for (int it = 0; it < 8; ++it) {
      int idx = it * 128 + tid;
      int r = idx >> 4, cc = idx & 15;
      *(uint4*)(sKh + r * FA_ST + cc * 8) =
          *(const uint4*)(src + (row0 + r) * HID + colbase + cc * 8);
    }
    __syncthreads();
    if (pass == 0) {
#pragma unroll
      for (int ks = 0; ks < 8; ++ks) ldsm_x4(qfh[ks], qaddr + ks * 32);
    } else {
#pragma unroll
      for (int ks = 0; ks < 8; ++ks) ldsm_x4(qfl[ks], qaddr + ks * 32);
    }
    __syncthreads();
  }

  float O[16][4];
#pragma unroll
  for (int j = 0; j < 16; ++j)
#pragma unroll
    for (int q = 0; q < 4; ++q) O[j][q] = 0.f;
  float m0 = -INFINITY, m1 = -INFINITY, l0 = 0.f, l1 = 0.f;
  const float scale = 0.08838834764831845f;

  int b_row = ((lane >> 4) << 3) + (lane & 7);
  int b_col8 = ((lane >> 3) & 1) << 3;

  for (int nb = 0; nb < SEQ / 64; ++nb) {
    size_t krow = (size_t)b * SEQ + nb * 64;
    __syncthreads();
#pragma unroll
    for (int it = 0; it < 8; ++it) {
      int idx = it * 128 + tid;
      int r = idx >> 4, cc = idx & 15;
      size_t goff = (krow + r) * HID + colbase + cc * 8;
      int soff = r * FA_ST + cc * 8;
      *(uint4*)(sKh + soff) = *(const uint4*)(kh + goff);
      *(uint4*)(sKl + soff) = *(const uint4*)(kl + goff);
      *(uint4*)(sV  + soff) = *(const uint4*)(vb + goff);
    }
    __syncthreads();

    // ---- S = Q K^T (3-pass hi/lo) ----
    float S[8][4];
#pragma unroll
    for (int j = 0; j < 8; ++j)
#pragma unroll
      for (int q = 0; q < 4; ++q) S[j][q] = 0.f;

#pragma unroll
    for (int ks = 0; ks < 8; ++ks) {
#pragma unroll
      for (int nj = 0; nj < 4; ++nj) {
        uint32_t off = (uint32_t)(((nj * 16 + b_row) * FA_ST +
                                   ks * 16 + b_col8) * 2);
        uint32_t rh[4], rl[4];
        ldsm_x4(rh, pKh + off);
        ldsm_x4(rl, pKl + off);
        mma16816(S[2 * nj],     qfh[ks], rh[0], rh[1]);
        mma16816(S[2 * nj + 1], qfh[ks], rh[2], rh[3]);
        mma16816(S[2 * nj],     qfh[ks], rl[0], rl[1]);
        mma16816(S[2 * nj + 1], qfh[ks], rl[2], rl[3]);
        mma16816(S[2 * nj],     qfl[ks], rh[0], rh[1]);
        mma16816(S[2 * nj + 1], qfl[ks], rh[2], rh[3]);
      }
    }

    // ---- online softmax (rows r = lane>>2 and r+8) ----
#pragma unroll
    for (int j = 0; j < 8; ++j)
#pragma unroll
      for (int q = 0; q < 4; ++q) S[j][q] *= scale;

    float mr0 = -INFINITY, mr1 = -INFINITY;
#pragma unroll
    for (int j = 0; j < 8; ++j) {
      mr0 = fmaxf(mr0, fmaxf(S[j][0], S[j][1]));
      mr1 = fmaxf(mr1, fmaxf(S[j][2], S[j][3]));
    }
    mr0 = fmaxf(mr0, __shfl_xor_sync(0xffffffffu, mr0, 1));
    mr0 = fmaxf(mr0, __shfl_xor_sync(0xffffffffu, mr0, 2));
    mr1 = fmaxf(mr1, __shfl_xor_sync(0xffffffffu, mr1, 1));
    mr1 = fmaxf(mr1, __shfl_xor_sync(0xffffffffu, mr1, 2));

    float mn0 = fmaxf(m0, mr0), mn1 = fmaxf(m1, mr1);
    float a0 = __expf(m0 - mn0), a1 = __expf(m1 - mn1);
    float s0 = 0.f, s1 = 0.f;
#pragma unroll
    for (int j = 0; j < 8; ++j) {
      S[j][0] = __expf(S[j][0] - mn0);
      S[j][1] = __expf(S[j][1] - mn0);
      S[j][2] = __expf(S[j][2] - mn1);
      S[j][3] = __expf(S[j][3] - mn1);
      s0 += S[j][0] + S[j][1];
      s1 += S[j][2] + S[j][3];
    }
    s0 += __shfl_xor_sync(0xffffffffu, s0, 1);
    s0 += __shfl_xor_sync(0xffffffffu, s0, 2);
    s1 += __shfl_xor_sync(0xffffffffu, s1, 1);
    s1 += __shfl_xor_sync(0xffffffffu, s1, 2);

    l0 = l0 * a0 + s0;
    l1 = l1 * a1 + s1;
    m0 = mn0; m1 = mn1;

#pragma unroll
    for (int j = 0; j < 16; ++j) {
      O[j][0] *= a0; O[j][1] *= a0;
      O[j][2] *= a1; O[j][3] *= a1;
    }

    // ---- P fragments (bf16) ----
    uint32_t pf[4][4];
#pragma unroll
    for (int t = 0; t < 4; ++t) {
      pf[t][0] = packbf(S[2 * t][0],     S[2 * t][1]);
      pf[t][1] = packbf(S[2 * t][2],     S[2 * t][3]);
      pf[t][2] = packbf(S[2 * t + 1][0], S[2 * t + 1][1]);
      pf[t][3] = packbf(S[2 * t + 1][2], S[2 * t + 1][3]);
    }

    // ---- O += P V ----
#pragma unroll
    for (int t = 0; t < 4; ++t) {
#pragma unroll
      for (int n16 = 0; n16 < 8; ++n16) {
        uint32_t voff = (uint32_t)(((t * 16 + (lane & 15)) * FA_ST +
                                    n16 * 16 + ((lane >> 4) << 3)) * 2);
        uint32_t rv[4];
        ldsm_x4_t(rv, pV + voff);
        mma16816(O[2 * n16],     pf[t], rv[0], rv[1]);
        mma16816(O[2 * n16 + 1], pf[t], rv[2], rv[3]);
      }
    }
  }

  // ---- epilogue: normalize and emit bf16 hi/lo planes ----
  float i0 = 1.0f / l0, i1 = 1.0f / l1;
  int r = lane >> 2, c2 = (lane & 3) * 2;
  size_t gr0 = row0 + w * 16 + r;
#pragma unroll
  for (int j = 0; j < 16; ++j) {
    int col = colbase + j * 8 + c2;
    float x0 = O[j][0] * i0, x1 = O[j][1] * i0;
    float y0 = O[j][2] * i1, y1 = O[j][3] * i1;
    __nv_bfloat16 h0, l0b, h1, l1b;
    split1(x0, h0, l0b); split1(x1, h1, l1b);
    *(uint32_t*)(ctxh + gr0 * HID + col) = packbf(__bfloat162float(h0), 0.f) ; // placeholder replaced below
    // write properly:
    {
      __nv_bfloat162 hp; hp.x = h0; hp.y = h1;
      __nv_bfloat162 lp; lp.x = l0b; lp.y = l1b;
      *(__nv_bfloat162*)(ctxh + gr0 * HID + col) = hp;
      *(__nv_bfloat162*)(ctxl + gr0 * HID + col) = lp;
    }
    split1(y0, h0, l0b); split1(y1, h1, l1b);
    {
      __nv_bfloat162 hp; hp.x = h0; hp.y = h1;
      __nv_bfloat162 lp; lp.x = l0b; lp.y = l1b;
      *(__nv_bfloat162*)(ctxh + (gr0 + 8) * HID + col) = hp;
      *(__nv_bfloat162*)(ctxl + (gr0 + 8) * HID + col) = lp;
    }
  }
}

// ---------------------------------------------------------------------------
// Transpose + split: W[K][N] fp32 -> hi/lo bf16 planes [N][K].
// ---------------------------------------------------------------------------
__global__ void __launch_bounds__(256) transpose_split_kernel(
    const float* __restrict__ in, __nv_bfloat16* __restrict__ oh,
    __nv_bfloat16* __restrict__ ol) {
  __shared__ float t[32][33];
  int tx = threadIdx.x, ty = threadIdx.y;
  int x = blockIdx.x * 32 + tx;
  int y0 = blockIdx.y * 32;
#pragma unroll
  for (int i = ty; i < 32; i += 8)
    t[i][tx] = in[(size_t)(y0 + i) * HID + x];
  __syncthreads();
  int ox = y0 + tx;
  int oy0 = blockIdx.x * 32;
#pragma unroll
  for (int i = ty; i < 32; i += 8) {
    float v = t[tx][i];
    __nv_bfloat16 h, l;
    split1(v, h, l);
    oh[(size_t)(oy0 + i) * HID + ox] = h;
    ol[(size_t)(oy0 + i) * HID + ox] = l;
  }
}

// ---------------------------------------------------------------------------
// RMSNorm -> bf16 hi/lo planes
// ---------------------------------------------------------------------------
__global__ void __launch_bounds__(256) rmsnorm_split_kernel(
    const float* __restrict__ x, const float* __restrict__ w,
    __nv_bfloat16* __restrict__ yh, __nv_bfloat16* __restrict__ yl) {
  int row = blockIdx.x;
  const float4* x4 = (const float4*)(x + (size_t)row * HID);
  const float4* w4 = (const float4*)w;
  int tid = threadIdx.x;

  float s = 0.f;
#pragma unroll
  for (int i = tid; i < HID / 4; i += 256) {
    float4 v = x4[i];
    s += v.x * v.x + v.y * v.y + v.z * v.z + v.w * v.w;
  }
#pragma unroll
  for (int off = 16; off > 0; off >>= 1)
    s += __shfl_xor_sync(0xffffffffu, s, off);

  __shared__ float red[8];
  __shared__ float s_inv;
  if ((tid & 31) == 0) red[tid >> 5] = s;
  __syncthreads();
  if (tid == 0) {
    float t = 0.f;
#pragma unroll
    for (int i = 0; i < 8; i++) t += red[i];
    s_inv = rsqrtf(t / (float)HID + EPS);
  }
  __syncthreads();
  float inv = s_inv;

#pragma unroll
  for (int i = tid; i < HID / 4; i += 256) {
    float4 v = x4[i];
    float4 ww = w4[i];
    float4 o;
    o.x = v.x * inv * ww.x;
    o.y = v.y * inv * ww.y;
    o.z = v.z * inv * ww.z;
    o.w = v.w * inv * ww.w;
    uint2 h, l;
    split4(o, h, l);
    *(uint2*)(yh + (size_t)row * HID + i * 4) = h;
    *(uint2*)(yl + (size_t)row * HID + i * 4) = l;
  }
}

// ---------------------------------------------------------------------------
// RoPE table; RoPE apply fp32 -> bf16 hi/lo planes; V convert.
// ---------------------------------------------------------------------------
__global__ void rope_table_kernel() {
  int idx = blockIdx.x * 256 + threadIdx.x;
  int s = idx >> 6;
  int d = idx & 63;
  float invf = 1.0f / powf(10000.0f, (float)d / 64.0f);
  float ang = (float)s * invf;
  g_cos[idx] = cosf(ang);
  g_sin[idx] = sinf(ang);
}

__global__ void __launch_bounds__(256) rope_split_kernel(
    const float* __restrict__ q, const float* __restrict__ k,
    __nv_bfloat16* __restrict__ qh, __nv_bfloat16* __restrict__ ql,
    __nv_bfloat16* __restrict__ kh, __nv_bfloat16* __restrict__ kl) {
  int idx = blockIdx.x * 256 + threadIdx.x;
  int d = idx & 63;
  int h = (idx >> 6) & 15;
  int row = idx >> 10;
  int s = row & (SEQ - 1);

  float c  = g_cos[s * 64 + d];
  float sn = g_sin[s * 64 + d];
  size_t base = (size_t)row * HID + h * HD + d;

  float q1 = q[base], q2 = q[base + 64];
  float r1 = q1 * c - q2 * sn;
  float r2 = q2 * c + q1 * sn;
  __nv_bfloat16 hh, ll;
  split1(r1, hh, ll); qh[base] = hh;      ql[base] = ll;
  split1(r2, hh, ll); qh[base + 64] = hh; ql[base + 64] = ll;

  float k1 = k[base], k2 = k[base + 64];
  r1 = k1 * c - k2 * sn;
  r2 = k2 * c + k1 * sn;
  split1(r1, hh, ll); kh[base] = hh;      kl[base] = ll;
  split1(r2, hh, ll); kh[base + 64] = hh; kl[base + 64] = ll;
}

__global__ void __launch_bounds__(256) vconv_kernel(
    const float* __restrict__ v, __nv_bfloat16* __restrict__ vb) {
  int idx = blockIdx.x * 256 + threadIdx.x;
  float4 f = ((const float4*)v)[idx];
  __nv_bfloat162 p0 = __floats2bfloat162_rn(f.x, f.y);
  __nv_bfloat162 p1 = __floats2bfloat162_rn(f.z, f.w);
  uint2 o;
  o.x = *reinterpret_cast<uint32_t*>(&p0);
  o.y = *reinterpret_cast<uint32_t*>(&p1);
  ((uint2*)vb)[idx] = o;
}

// ---------------------------------------------------------------------------
// SiLU(g1)*g3 -> bf16 hi/lo planes
// ---------------------------------------------------------------------------
__global__ void __launch_bounds__(256) silumul_split_kernel(
    const float* __restrict__ a, const float* __restrict__ b,
    __nv_bfloat16* __restrict__ th, __nv_bfloat16* __restrict__ tl) {
  int idx = blockIdx.x * 256 + threadIdx.x;
  float4 va = ((const float4*)a)[idx];
  float4 vb = ((const float4*)b)[idx];
  float4 vc;
  vc.x = va.x / (1.f + __expf(-va.x)) * vb.x;
  vc.y = va.y / (1.f + __expf(-va.y)) * vb.y;
  vc.z = va.z / (1.f + __expf(-va.z)) * vb.z;
  vc.w = va.w / (1.f + __expf(-va.w)) * vb.w;
  uint2 h, l;
  split4(vc, h, l);
  ((uint2*)th)[idx] = h;
  ((uint2*)tl)[idx] = l;
}

// ---------------------------------------------------------------------------
// Launch
// ---------------------------------------------------------------------------
extern "C" void kernel_launch(void* const* d_in, const int* in_sizes, int n_in,
                              void* d_out, int out_size) {
  const float* hidden = (const float*)d_in[0];
  const float* Wq = (const float*)d_in[1];
  const float* Wk = (const float*)d_in[2];
  const float* Wv = (const float*)d_in[3];
  const float* Wo = (const float*)d_in[4];
  const float* w1 = (const float*)d_in[5];
  const float* w2 = (const float*)d_in[6];
  const float* w3 = (const float*)d_in[7];
  const float* ln1 = (const float*)d_in[8];
  const float* ln2 = (const float*)d_in[9];
  float* out = (float*)d_out;

  float *p_qf, *p_kf, *p_vf, *p_h, *p_g1, *p_g3;
  __nv_bfloat16 *p_xnh, *p_xnl, *p_qh, *p_ql, *p_kh, *p_kl, *p_vb;
  __nv_bfloat16 *p_ch, *p_cl, *p_ynh, *p_ynl, *p_th, *p_tl, *p_wth, *p_wtl;
  cudaGetSymbolAddress((void**)&p_qf, g_qf);
  cudaGetSymbolAddress((void**)&p_kf, g_kf);
  cudaGetSymbolAddress((void**)&p_vf, g_vf);
  cudaGetSymbolAddress((void**)&p_h, g_h);
  cudaGetSymbolAddress((void**)&p_g1, g_g1);
  cudaGetSymbolAddress((void**)&p_g3, g_g3);
  cudaGetSymbolAddress((void**)&p_xnh, g_xnh);
  cudaGetSymbolAddress((void**)&p_xnl, g_xnl);
  cudaGetSymbolAddress((void**)&p_qh, g_qh);
  cudaGetSymbolAddress((void**)&p_ql, g_ql);
  cudaGetSymbolAddress((void**)&p_kh, g_kh);
  cudaGetSymbolAddress((void**)&p_kl, g_kl);
  cudaGetSymbolAddress((void**)&p_vb, g_vb);
  cudaGetSymbolAddress((void**)&p_ch, g_ch);
  cudaGetSymbolAddress((void**)&p_cl, g_cl);
  cudaGetSymbolAddress((void**)&p_ynh, g_ynh);
  cudaGetSymbolAddress((void**)&p_ynl, g_ynl);
  cudaGetSymbolAddress((void**)&p_th, g_th);
  cudaGetSymbolAddress((void**)&p_tl, g_tl);
  cudaGetSymbolAddress((void**)&p_wth, g_wth);
  cudaGetSymbolAddress((void**)&p_wtl, g_wtl);

  static bool attr_set = false;
  if (!attr_set) {
    cudaFuncSetAttribute(flash_mma_kernel,
                         cudaFuncAttributeMaxDynamicSharedMemorySize, FA_SMEM);
    cudaFuncSetAttribute(gemm_tc_kernel<false>,
                         cudaFuncAttributeMaxDynamicSharedMemorySize, GEMM_SMEM);
    cudaFuncSetAttribute(gemm_tc_kernel<true>,
                         cudaFuncAttributeMaxDynamicSharedMemorySize, GEMM_SMEM);
    attr_set = true;
  }

  __nv_bfloat16* wh[7];
  __nv_bfloat16* wl[7];
  for (int i = 0; i < 7; i++) {
    wh[i] = p_wth + (size_t)i * N2;
    wl[i] = p_wtl + (size_t)i * N2;
  }
  const float* wsrc[7] = {Wq, Wk, Wv, Wo, w1, w3, w2};

  dim3 tgrid(64, 64);
  dim3 tblk(32, 8);
  for (int i = 0; i < 7; i++)
    transpose_split_kernel<<<tgrid, tblk>>>(wsrc[i], wh[i], wl[i]);

  rmsnorm_split_kernel<<<MROWS, 256>>>(hidden, ln1, p_xnh, p_xnl);
  rope_table_kernel<<<(SEQ * 64) / 256, 256>>>();

  // QKV projections (z = 3)
  dim3 qkv_grid(HID / BN, MROWS / BM, 3);
  gemm_tc_kernel<false><<<qkv_grid, 256, GEMM_SMEM>>>(
      p_xnh, p_xnl, wh[0], wl[0], wh[1], wl[1], wh[2], wl[2],
      nullptr, p_qf, p_kf, p_vf);

  rope_split_kernel<<<(MROWS * NH * 64) / 256, 256>>>(
      p_qf, p_kf, p_qh, p_ql, p_kh, p_kl);
  vconv_kernel<<<(MROWS * HID / 4) / 256, 256>>>(p_vf, p_vb);

  flash_mma_kernel<<<dim3(SEQ / 64, BATCH * NH), 128, FA_SMEM>>>(
      p_qh, p_ql, p_kh, p_kl, p_vb, p_ch, p_cl);

  // Output projection + residual
  dim3 g1_grid(HID / BN, MROWS / BM, 1);
  gemm_tc_kernel<true><<<g1_grid, 256, GEMM_SMEM>>>(
      p_ch, p_cl, wh[3], wl[3], nullptr, nullptr, nullptr, nullptr,
      hidden, p_h, nullptr, nullptr);

  rmsnorm_split_kernel<<<MROWS, 256>>>(p_h, ln2, p_ynh, p_ynl);

  // MLP up + gate (z = 2)
  dim3 g2_grid(HID / BN, MROWS / BM, 2);
  gemm_tc_kernel<false><<<g2_grid, 256, GEMM_SMEM>>>(
      p_ynh, p_ynl, wh[4], wl[4], wh[5], wl[5], nullptr, nullptr,
      nullptr, p_g1, p_g3, nullptr);

  silumul_split_kernel<<<(MROWS * HID / 4) / 256, 256>>>(p_g1, p_g3, p_th, p_tl);

  // Down projection + residual -> output
  gemm_tc_kernel<true><<<g1_grid, 256, GEMM_SMEM>>>(
      p_th, p_tl, wh[6], wl[6], nullptr, nullptr, nullptr, nullptr,
      p_h, out, nullptr, nullptr);
}

// round 5
// speedup vs baseline: 3.4098x; 1.1636x over previous
#include <cuda_runtime.h>
#include <cuda_bf16.h>
#include <math.h>
#include <stdint.h>

// ---------------------------------------------------------------------------
// Problem constants: B=2, S=2048, HID=2048, NH=16, HD=128, fp32 in/out.
// ---------------------------------------------------------------------------
#define BATCH 2
#define SEQ   2048
#define HID   2048
#define NH    16
#define HD    128
#define MROWS (BATCH * SEQ)
#define EPS   1e-6f
#define N2    (HID * HID)

// ---------------------------------------------------------------------------
// Scratch (device globals)
// ---------------------------------------------------------------------------
__device__ float g_qf [MROWS * HID];
__device__ float g_kf [MROWS * HID];
__device__ float g_h  [MROWS * HID];
__device__ float g_g1 [MROWS * HID];
__device__ float g_g3 [MROWS * HID];
__device__ __nv_bfloat16 g_xnh[MROWS * HID], g_xnl[MROWS * HID];
__device__ __nv_bfloat16 g_qh [MROWS * HID], g_ql [MROWS * HID];
__device__ __nv_bfloat16 g_kh [MROWS * HID], g_kl [MROWS * HID];
__device__ __nv_bfloat16 g_vb [MROWS * HID];
__device__ __nv_bfloat16 g_ch [MROWS * HID], g_cl [MROWS * HID];
__device__ __nv_bfloat16 g_ynh[MROWS * HID], g_ynl[MROWS * HID];
__device__ __nv_bfloat16 g_th [MROWS * HID], g_tl [MROWS * HID];
__device__ __nv_bfloat16 g_wth[7 * N2], g_wtl[7 * N2];
__device__ float g_cos[SEQ * (HD / 2)];
__device__ float g_sin[SEQ * (HD / 2)];

// ---------------------------------------------------------------------------
// PTX helpers
// ---------------------------------------------------------------------------
__device__ __forceinline__ uint32_t smem_u32(const void* p) {
  uint32_t a;
  asm("{ .reg .u64 t; cvta.to.shared.u64 t, %1; cvt.u32.u64 %0, t; }"
      : "=r"(a) : "l"(p));
  return a;
}
__device__ __forceinline__ void ldsm_x4(uint32_t (&r)[4], uint32_t addr) {
  asm volatile("ldmatrix.sync.aligned.m8n8.x4.shared.b16 {%0,%1,%2,%3}, [%4];"
               : "=r"(r[0]), "=r"(r[1]), "=r"(r[2]), "=r"(r[3]) : "r"(addr));
}
__device__ __forceinline__ void ldsm_x4_t(uint32_t (&r)[4], uint32_t addr) {
  asm volatile("ldmatrix.sync.aligned.m8n8.x4.trans.shared.b16 {%0,%1,%2,%3}, [%4];"
               : "=r"(r[0]), "=r"(r[1]), "=r"(r[2]), "=r"(r[3]) : "r"(addr));
}
__device__ __forceinline__ void mma16816(float (&d)[4], const uint32_t (&a)[4],
                                         const uint32_t b0, const uint32_t b1) {
  asm volatile(
      "mma.sync.aligned.m16n8k16.row.col.f32.bf16.bf16.f32 "
      "{%0,%1,%2,%3}, {%4,%5,%6,%7}, {%8,%9}, {%0,%1,%2,%3};"
      : "+f"(d[0]), "+f"(d[1]), "+f"(d[2]), "+f"(d[3])
      : "r"(a[0]), "r"(a[1]), "r"(a[2]), "r"(a[3]), "r"(b0), "r"(b1));
}
__device__ __forceinline__ void cp16(uint32_t dst, const void* src) {
  asm volatile("cp.async.cg.shared.global [%0], [%1], 16;"
               :: "r"(dst), "l"(src));
}
#define CP_COMMIT asm volatile("cp.async.commit_group;" ::: "memory")
#define CP_WAIT0  asm volatile("cp.async.wait_group 0;" ::: "memory")
#define CP_WAIT1  asm volatile("cp.async.wait_group 1;" ::: "memory")

__device__ __forceinline__ uint32_t packbf(float a, float b) {
  __nv_bfloat162 p = __floats2bfloat162_rn(a, b);
  return *reinterpret_cast<uint32_t*>(&p);
}
__device__ __forceinline__ void split1(float x, __nv_bfloat16& h, __nv_bfloat16& l) {
  h = __float2bfloat16_rn(x);
  l = __float2bfloat16_rn(x - __bfloat162float(h));
}
__device__ __forceinline__ void split4(float4 v, uint2& hi, uint2& lo) {
  __nv_bfloat162 h0 = __floats2bfloat162_rn(v.x, v.y);
  __nv_bfloat162 h1 = __floats2bfloat162_rn(v.z, v.w);
  float2 f0 = __bfloat1622float2(h0);
  float2 f1 = __bfloat1622float2(h1);
  __nv_bfloat162 l0 = __floats2bfloat162_rn(v.x - f0.x, v.y - f0.y);
  __nv_bfloat162 l1 = __floats2bfloat162_rn(v.z - f1.x, v.w - f1.y);
  hi.x = *reinterpret_cast<uint32_t*>(&h0);
  hi.y = *reinterpret_cast<uint32_t*>(&h1);
  lo.x = *reinterpret_cast<uint32_t*>(&l0);
  lo.y = *reinterpret_cast<uint32_t*>(&l1);
}

// ---------------------------------------------------------------------------
// GEMM: C[M,N] = A @ B^T (+D). bf16 hi/lo planes, cp.async double-buffered.
// CTA 128x128, KC=64, 8 warps (2Mx4N), warp tile 64x32, 3-pass hi/lo.
// ---------------------------------------------------------------------------
#define BM 128
#define BN 128
#define KC 64
#define SA_BYTES 144
#define PLANE_BYTES (128 * SA_BYTES)
#define STAGE_BYTES (4 * PLANE_BYTES)
#define GEMM_SMEM (2 * STAGE_BYTES)

template <bool ADD>
__global__ void __launch_bounds__(256) gemm_tc_kernel(
    const __nv_bfloat16* __restrict__ Ah, const __nv_bfloat16* __restrict__ Al,
    const __nv_bfloat16* __restrict__ Bh0, const __nv_bfloat16* __restrict__ Bl0,
    const __nv_bfloat16* __restrict__ Bh1, const __nv_bfloat16* __restrict__ Bl1,
    const __nv_bfloat16* __restrict__ Bh2, const __nv_bfloat16* __restrict__ Bl2,
    const float* __restrict__ Dres,
    float* __restrict__ C0, float* __restrict__ C1, float* __restrict__ C2,
    __nv_bfloat16* __restrict__ Vb2) {
  const __nv_bfloat16* Bh = (blockIdx.z == 0) ? Bh0 : (blockIdx.z == 1 ? Bh1 : Bh2);
  const __nv_bfloat16* Bl = (blockIdx.z == 0) ? Bl0 : (blockIdx.z == 1 ? Bl1 : Bl2);
  float* C = (blockIdx.z == 0) ? C0 : (blockIdx.z == 1 ? C1 : C2);
  __nv_bfloat16* Cb = (blockIdx.z == 2) ? Vb2 : nullptr;

  extern __shared__ char sm[];
  uint32_t sbase = smem_u32(sm);

  int tid  = threadIdx.x;
  int lane = tid & 31;
  int wid  = tid >> 5;
  int wm   = wid & 1;
  int wn   = wid >> 1;
  int m0 = blockIdx.y * BM;
  int n0 = blockIdx.x * BN;

  const __nv_bfloat16* Agh = Ah + (size_t)m0 * HID;
  const __nv_bfloat16* Agl = Al + (size_t)m0 * HID;
  const __nv_bfloat16* Bgh = Bh + (size_t)n0 * HID;
  const __nv_bfloat16* Bgl = Bl + (size_t)n0 * HID;

  float acc[4][4][4];
#pragma unroll
  for (int i = 0; i < 4; i++)
#pragma unroll
    for (int j = 0; j < 4; j++)
#pragma unroll
      for (int q = 0; q < 4; q++) acc[i][j][q] = 0.f;

#define CPYA(dst, src, kc) do {                                               \
    _Pragma("unroll")                                                         \
    for (int it = 0; it < 4; ++it) {                                          \
      int idx = it * 256 + tid;                                               \
      int r = idx >> 3, cc = idx & 7;                                         \
      cp16((dst) + r * SA_BYTES + cc * 16,                                    \
           (src) + (size_t)r * HID + (kc) + cc * 8);                          \
    }                                                                         \
  } while (0)

#define STAGE_A(s, c) do {                                                    \
    uint32_t base = sbase + (s) * STAGE_BYTES;                                \
    int kc = (c) * KC;                                                        \
    CPYA(base,                   Agh, kc);                                    \
    CPYA(base + PLANE_BYTES,     Agl, kc);                                    \
    CPYA(base + 2 * PLANE_BYTES, Bgh, kc);                                    \
    CPYA(base + 3 * PLANE_BYTES, Bgl, kc);                                    \
  } while (0)

  int a_row = wm * 64 + (lane & 15);
  int a_col8 = (lane >> 4) << 3;
  int b_row = wn * 32 + ((lane >> 4) << 3) + (lane & 7);
  int b_col8 = ((lane >> 3) & 1) << 3;

  STAGE_A(0, 0);
  CP_COMMIT;

  const int NCHUNK = HID / KC;
  int stage = 0;

  for (int c = 0; c < NCHUNK; ++c) {
    if (c + 1 < NCHUNK) {
      STAGE_A(stage ^ 1, c + 1);
      CP_COMMIT;
      CP_WAIT1;
    } else {
      CP_WAIT0;
    }
    __syncthreads();

    uint32_t pAhi = sbase + stage * STAGE_BYTES;
    uint32_t pAlo = pAhi + PLANE_BYTES;
    uint32_t pBhi = pAhi + 2 * PLANE_BYTES;
    uint32_t pBlo = pAhi + 3 * PLANE_BYTES;

#pragma unroll
    for (int ks = 0; ks < 4; ++ks) {
      int kbase = ks * 16;
      uint32_t ahi[4][4], alo[4][4];
#pragma unroll
      for (int mi = 0; mi < 4; ++mi) {
        uint32_t off = (uint32_t)((a_row + mi * 16) * SA_BYTES +
                                  (kbase + a_col8) * 2);
        ldsm_x4(ahi[mi], pAhi + off);
        ldsm_x4(alo[mi], pAlo + off);
      }
      uint32_t bhi[4][2], blo[4][2];
#pragma unroll
      for (int nj = 0; nj < 2; ++nj) {
        uint32_t off = (uint32_t)((b_row + nj * 16) * SA_BYTES +
                                  (kbase + b_col8) * 2);
        uint32_t rh[4], rl[4];
        ldsm_x4(rh, pBhi + off);
        ldsm_x4(rl, pBlo + off);
        bhi[nj * 2 + 0][0] = rh[0]; bhi[nj * 2 + 0][1] = rh[1];
        bhi[nj * 2 + 1][0] = rh[2]; bhi[nj * 2 + 1][1] = rh[3];
        blo[nj * 2 + 0][0] = rl[0]; blo[nj * 2 + 0][1] = rl[1];
        blo[nj * 2 + 1][0] = rl[2]; blo[nj * 2 + 1][1] = rl[3];
      }
#pragma unroll
      for (int mi = 0; mi < 4; ++mi)
#pragma unroll
        for (int nt = 0; nt < 4; ++nt) {
          mma16816(acc[mi][nt], ahi[mi], bhi[nt][0], bhi[nt][1]);
          mma16816(acc[mi][nt], ahi[mi], blo[nt][0], blo[nt][1]);
          mma16816(acc[mi][nt], alo[mi], bhi[nt][0], bhi[nt][1]);
        }
    }
    __syncthreads();
    stage ^= 1;
  }
#undef STAGE_A
#undef CPYA

  int er = m0 + wm * 64 + (lane >> 2);
  int ec = n0 + wn * 32 + (lane & 3) * 2;
#pragma unroll
  for (int mi = 0; mi < 4; ++mi) {
#pragma unroll
    for (int nt = 0; nt < 4; ++nt) {
      size_t o0 = (size_t)(er + mi * 16) * HID + ec + nt * 8;
      size_t o1 = o0 + 8 * HID;
      if (Cb) {
        *(uint32_t*)(Cb + o0) = packbf(acc[mi][nt][0], acc[mi][nt][1]);
        *(uint32_t*)(Cb + o1) = packbf(acc[mi][nt][2], acc[mi][nt][3]);
      } else {
        float2 v0 = make_float2(acc[mi][nt][0], acc[mi][nt][1]);
        float2 v1 = make_float2(acc[mi][nt][2], acc[mi][nt][3]);
        if (ADD) {
          float2 d0 = *(const float2*)(Dres + o0);
          float2 d1 = *(const float2*)(Dres + o1);
          v0.x += d0.x; v0.y += d0.y;
          v1.x += d1.x; v1.y += d1.y;
        }
        *(float2*)(C + o0) = v0;
        *(float2*)(C + o1) = v1;
      }
    }
  }
}

// ---------------------------------------------------------------------------
// Flash attention, mma.sync, cp.async double-buffered K/Kl/V stages.
// 64 q-rows/CTA, 4 warps, BN=64, HD=128.
// ---------------------------------------------------------------------------
#define FA_ST 136
#define FA_PL2 (64 * FA_ST * 2)            // plane bytes = 17408
#define FA_STAGE_BYTES (3 * FA_PL2)        // 52224
#define FA_SMEM (2 * FA_STAGE_BYTES)       // 104448

__global__ void __launch_bounds__(128) flash_mma_kernel(
    const __nv_bfloat16* __restrict__ qh, const __nv_bfloat16* __restrict__ ql,
    const __nv_bfloat16* __restrict__ kh, const __nv_bfloat16* __restrict__ kl,
    const __nv_bfloat16* __restrict__ vb,
    __nv_bfloat16* __restrict__ ctxh, __nv_bfloat16* __restrict__ ctxl) {
  extern __shared__ char smc[];
  uint32_t pS = smem_u32(smc);

  int qb = blockIdx.x;
  int bh = blockIdx.y;
  int b = bh >> 4, h = bh & 15;
  int tid = threadIdx.x;
  int lane = tid & 31;
  int w = tid >> 5;
  int colbase = h * HD;
  size_t row0 = (size_t)b * SEQ + qb * 64;

  // ---- load Q fragments (hi then lo), staged through stage-0 plane 0 ----
  __nv_bfloat16* sQ = (__nv_bfloat16*)smc;
  uint32_t qfh[8][4], qfl[8][4];
  uint32_t qaddr = pS + (uint32_t)(((w * 16 + (lane & 15)) * FA_ST +
                                    ((lane >> 4) << 3)) * 2);
#pragma unroll
  for (int pass = 0; pass < 2; ++pass) {
    const __nv_bfloat16* src = pass ? ql : qh;
#pragma unroll
    for (int it = 0; it < 8; ++it) {
      int idx = it * 128 + tid;
      int r = idx >> 4, cc = idx & 15;
      *(uint4*)(sQ + r * FA_ST + cc * 8) =
          *(const uint4*)(src + (row0 + r) * HID + colbase + cc * 8);
    }
    __syncthreads();
    if (pass == 0) {
#pragma unroll
      for (int ks = 0; ks < 8; ++ks) ldsm_x4(qfh[ks], qaddr + ks * 32);
    } else {
#pragma unroll
      for (int ks = 0; ks < 8; ++ks) ldsm_x4(qfl[ks], qaddr + ks * 32);
    }
    __syncthreads();
  }

#define FA_PREFETCH(st, nb) do {                                              \
    size_t krow = (size_t)b * SEQ + (size_t)(nb) * 64;                        \
    uint32_t stb = pS + (st) * FA_STAGE_BYTES;                                \
    _Pragma("unroll")                                                         \
    for (int it = 0; it < 8; ++it) {                                          \
      int idx = it * 128 + tid;                                               \
      int r = idx >> 4, cc = idx & 15;                                        \
      size_t goff = (krow + r) * HID + colbase + cc * 8;                      \
      uint32_t so = (uint32_t)(r * (FA_ST * 2) + cc * 16);                    \
      cp16(stb + so,              kh + goff);                                 \
      cp16(stb + FA_PL2 + so,     kl + goff);                                 \
      cp16(stb + 2 * FA_PL2 + so, vb + goff);                                 \
    }                                                                         \
  } while (0)

  float O[16][4];
#pragma unroll
  for (int j = 0; j < 16; ++j)
#pragma unroll
    for (int q = 0; q < 4; ++q) O[j][q] = 0.f;
  float m0 = -INFINITY, m1 = -INFINITY, l0 = 0.f, l1 = 0.f;
  const float scale = 0.08838834764831845f;

  int b_row = ((lane >> 4) << 3) + (lane & 7);
  int b_col8 = ((lane >> 3) & 1) << 3;

  FA_PREFETCH(0, 0);
  CP_COMMIT;

  const int NB = SEQ / 64;
  int st = 0;

  for (int nb = 0; nb < NB; ++nb) {
    if (nb + 1 < NB) {
      FA_PREFETCH(st ^ 1, nb + 1);
      CP_COMMIT;
      CP_WAIT1;
    } else {
      CP_WAIT0;
    }
    __syncthreads();

    uint32_t pKh = pS + st * FA_STAGE_BYTES;
    uint32_t pKl = pKh + FA_PL2;
    uint32_t pV  = pKh + 2 * FA_PL2;

    // ---- S = Q K^T (3-pass hi/lo) ----
    float S[8][4];
#pragma unroll
    for (int j = 0; j < 8; ++j)
#pragma unroll
      for (int q = 0; q < 4; ++q) S[j][q] = 0.f;

#pragma unroll
    for (int ks = 0; ks < 8; ++ks) {
#pragma unroll
      for (int nj = 0; nj < 4; ++nj) {
        uint32_t off = (uint32_t)(((nj * 16 + b_row) * FA_ST +
                                   ks * 16 + b_col8) * 2);
        uint32_t rh[4], rl[4];
        ldsm_x4(rh, pKh + off);
        ldsm_x4(rl, pKl + off);
        mma16816(S[2 * nj],     qfh[ks], rh[0], rh[1]);
        mma16816(S[2 * nj + 1], qfh[ks], rh[2], rh[3]);
        mma16816(S[2 * nj],     qfh[ks], rl[0], rl[1]);
        mma16816(S[2 * nj + 1], qfh[ks], rl[2], rl[3]);
        mma16816(S[2 * nj],     qfl[ks], rh[0], rh[1]);
        mma16816(S[2 * nj + 1], qfl[ks], rh[2], rh[3]);
      }
    }

    // ---- online softmax ----
#pragma unroll
    for (int j = 0; j < 8; ++j)
#pragma unroll
      for (int q = 0; q < 4; ++q) S[j][q] *= scale;

    float mr0 = -INFINITY, mr1 = -INFINITY;
#pragma unroll
    for (int j = 0; j < 8; ++j) {
      mr0 = fmaxf(mr0, fmaxf(S[j][0], S[j][1]));
      mr1 = fmaxf(mr1, fmaxf(S[j][2], S[j][3]));
    }
    mr0 = fmaxf(mr0, __shfl_xor_sync(0xffffffffu, mr0, 1));
    mr0 = fmaxf(mr0, __shfl_xor_sync(0xffffffffu, mr0, 2));
    mr1 = fmaxf(mr1, __shfl_xor_sync(0xffffffffu, mr1, 1));
    mr1 = fmaxf(mr1, __shfl_xor_sync(0xffffffffu, mr1, 2));

    float mn0 = fmaxf(m0, mr0), mn1 = fmaxf(m1, mr1);
    float a0 = __expf(m0 - mn0), a1 = __expf(m1 - mn1);
    float s0 = 0.f, s1 = 0.f;
#pragma unroll
    for (int j = 0; j < 8; ++j) {
      S[j][0] = __expf(S[j][0] - mn0);
      S[j][1] = __expf(S[j][1] - mn0);
      S[j][2] = __expf(S[j][2] - mn1);
      S[j][3] = __expf(S[j][3] - mn1);
      s0 += S[j][0] + S[j][1];
      s1 += S[j][2] + S[j][3];
    }
    s0 += __shfl_xor_sync(0xffffffffu, s0, 1);
    s0 += __shfl_xor_sync(0xffffffffu, s0, 2);
    s1 += __shfl_xor_sync(0xffffffffu, s1, 1);
    s1 += __shfl_xor_sync(0xffffffffu, s1, 2);

    l0 = l0 * a0 + s0;
    l1 = l1 * a1 + s1;
    m0 = mn0; m1 = mn1;

#pragma unroll
    for (int j = 0; j < 16; ++j) {
      O[j][0] *= a0; O[j][1] *= a0;
      O[j][2] *= a1; O[j][3] *= a1;
    }

    uint32_t pf[4][4];
#pragma unroll
    for (int t = 0; t < 4; ++t) {
      pf[t][0] = packbf(S[2 * t][0],     S[2 * t][1]);
      pf[t][1] = packbf(S[2 * t][2],     S[2 * t][3]);
      pf[t][2] = packbf(S[2 * t + 1][0], S[2 * t + 1][1]);
      pf[t][3] = packbf(S[2 * t + 1][2], S[2 * t + 1][3]);
    }

#pragma unroll
    for (int t = 0; t < 4; ++t) {
#pragma unroll
      for (int n16 = 0; n16 < 8; ++n16) {
        uint32_t voff = (uint32_t)(((t * 16 + (lane & 15)) * FA_ST +
                                    n16 * 16 + ((lane >> 4) << 3)) * 2);
        uint32_t rv[4];
        ldsm_x4_t(rv, pV + voff);
        mma16816(O[2 * n16],     pf[t], rv[0], rv[1]);
        mma16816(O[2 * n16 + 1], pf[t], rv[2], rv[3]);
      }
    }
    __syncthreads();
    st ^= 1;
  }
#undef FA_PREFETCH

  // ---- epilogue: normalize, emit bf16 hi/lo planes ----
  float i0 = 1.0f / l0, i1 = 1.0f / l1;
  int r = lane >> 2, c2 = (lane & 3) * 2;
  size_t gr0 = row0 + w * 16 + r;
#pragma unroll
  for (int j = 0; j < 16; ++j) {
    int col = colbase + j * 8 + c2;
    float x0 = O[j][0] * i0, x1 = O[j][1] * i0;
    float y0 = O[j][2] * i1, y1 = O[j][3] * i1;
    __nv_bfloat16 h0, lo0, h1, lo1;
    split1(x0, h0, lo0); split1(x1, h1, lo1);
    {
      __nv_bfloat162 hp; hp.x = h0; hp.y = h1;
      __nv_bfloat162 lp; lp.x = lo0; lp.y = lo1;
      *(__nv_bfloat162*)(ctxh + gr0 * HID + col) = hp;
      *(__nv_bfloat162*)(ctxl + gr0 * HID + col) = lp;
    }
    split1(y0, h0, lo0); split1(y1, h1, lo1);
    {
      __nv_bfloat162 hp; hp.x = h0; hp.y = h1;
      __nv_bfloat162 lp; lp.x = lo0; lp.y = lo1;
      *(__nv_bfloat162*)(ctxh + (gr0 + 8) * HID + col) = hp;
      *(__nv_bfloat162*)(ctxl + (gr0 + 8) * HID + col) = lp;
    }
  }
}

// ---------------------------------------------------------------------------
// All-weights transpose + split in one launch (z = weight index)
// ---------------------------------------------------------------------------
struct WPack {
  const float* src[7];
  __nv_bfloat16* oh[7];
  __nv_bfloat16* ol[7];
};

__global__ void __launch_bounds__(256) transpose_split_all(WPack p) {
  const float* in = p.src[blockIdx.z];
  __nv_bfloat16* oh = p.oh[blockIdx.z];
  __nv_bfloat16* ol = p.ol[blockIdx.z];
  __shared__ float t[32][33];
  int tx = threadIdx.x, ty = threadIdx.y;
  int x = blockIdx.x * 32 + tx;
  int y0 = blockIdx.y * 32;
#pragma unroll
  for (int i = ty; i < 32; i += 8)
    t[i][tx] = in[(size_t)(y0 + i) * HID + x];
  __syncthreads();
  int ox = y0 + tx;
  int oy0 = blockIdx.x * 32;
#pragma unroll
  for (int i = ty; i < 32; i += 8) {
    float v = t[tx][i];
    __nv_bfloat16 h, l;
    split1(v, h, l);
    oh[(size_t)(oy0 + i) * HID + ox] = h;
    ol[(size_t)(oy0 + i) * HID + ox] = l;
  }
}

// ---------------------------------------------------------------------------
// RMSNorm -> bf16 hi/lo planes
// ---------------------------------------------------------------------------
__global__ void __launch_bounds__(256) rmsnorm_split_kernel(
    const float* __restrict__ x, const float* __restrict__ w,
    __nv_bfloat16* __restrict__ yh, __nv_bfloat16* __restrict__ yl) {
  int row = blockIdx.x;
  const float4* x4 = (const float4*)(x + (size_t)row * HID);
  const float4* w4 = (const float4*)w;
  int tid = threadIdx.x;

  float s = 0.f;
#pragma unroll
  for (int i = tid; i < HID / 4; i += 256) {
    float4 v = x4[i];
    s += v.x * v.x + v.y * v.y + v.z * v.z + v.w * v.w;
  }
#pragma unroll
  for (int off = 16; off > 0; off >>= 1)
    s += __shfl_xor_sync(0xffffffffu, s, off);

  __shared__ float red[8];
  __shared__ float s_inv;
  if ((tid & 31) == 0) red[tid >> 5] = s;
  __syncthreads();
  if (tid == 0) {
    float t = 0.f;
#pragma unroll
    for (int i = 0; i < 8; i++) t += red[i];
    s_inv = rsqrtf(t / (float)HID + EPS);
  }
  __syncthreads();
  float inv = s_inv;

#pragma unroll
  for (int i = tid; i < HID / 4; i += 256) {
    float4 v = x4[i];
    float4 ww = w4[i];
    float4 o;
    o.x = v.x * inv * ww.x;
    o.y = v.y * inv * ww.y;
    o.z = v.z * inv * ww.z;
    o.w = v.w * inv * ww.w;
    uint2 h, l;
    split4(o, h, l);
    *(uint2*)(yh + (size_t)row * HID + i * 4) = h;
    *(uint2*)(yl + (size_t)row * HID + i * 4) = l;
  }
}

// ---------------------------------------------------------------------------
// RoPE table + apply (fp32 q,k -> bf16 hi/lo planes)
// ---------------------------------------------------------------------------
__global__ void rope_table_kernel() {
  int idx = blockIdx.x * 256 + threadIdx.x;
  int s = idx >> 6;
  int d = idx & 63;
  float invf = 1.0f / powf(10000.0f, (float)d / 64.0f);
  float ang = (float)s * invf;
  g_cos[idx] = cosf(ang);
  g_sin[idx] = sinf(ang);
}

__global__ void __launch_bounds__(256) rope_split_kernel(
    const float* __restrict__ q, const float* __restrict__ k,
    __nv_bfloat16* __restrict__ qh, __nv_bfloat16* __restrict__ ql,
    __nv_bfloat16* __restrict__ kh, __nv_bfloat16* __restrict__ kl) {
  int idx = blockIdx.x * 256 + threadIdx.x;
  int d = idx & 63;
  int h = (idx >> 6) & 15;
  int row = idx >> 10;
  int s = row & (SEQ - 1);

  float c  = g_cos[s * 64 + d];
  float sn = g_sin[s * 64 + d];
  size_t base = (size_t)row * HID + h * HD + d;

  float q1 = q[base], q2 = q[base + 64];
  float r1 = q1 * c - q2 * sn;
  float r2 = q2 * c + q1 * sn;
  __nv_bfloat16 hh, ll;
  split1(r1, hh, ll); qh[base] = hh;      ql[base] = ll;
  split1(r2, hh, ll); qh[base + 64] = hh; ql[base + 64] = ll;

  float k1 = k[base], k2 = k[base + 64];
  r1 = k1 * c - k2 * sn;
  r2 = k2 * c + k1 * sn;
  split1(r1, hh, ll); kh[base] = hh;      kl[base] = ll;
  split1(r2, hh, ll); kh[base + 64] = hh; kl[base + 64] = ll;
}

// ---------------------------------------------------------------------------
// SiLU(g1)*g3 -> bf16 hi/lo planes
// ---------------------------------------------------------------------------
__global__ void __launch_bounds__(256) silumul_split_kernel(
    const float* __restrict__ a, const float* __restrict__ b,
    __nv_bfloat16* __restrict__ th, __nv_bfloat16* __restrict__ tl) {
  int idx = blockIdx.x * 256 + threadIdx.x;
  float4 va = ((const float4*)a)[idx];
  float4 vb = ((const float4*)b)[idx];
  float4 vc;
  vc.x = va.x / (1.f + __expf(-va.x)) * vb.x;
  vc.y = va.y / (1.f + __expf(-va.y)) * vb.y;
  vc.z = va.z / (1.f + __expf(-va.z)) * vb.z;
  vc.w = va.w / (1.f + __expf(-va.w)) * vb.w;
  uint2 h, l;
  split4(vc, h, l);
  ((uint2*)th)[idx] = h;
  ((uint2*)tl)[idx] = l;
}

// ---------------------------------------------------------------------------
// Launch
// ---------------------------------------------------------------------------
extern "C" void kernel_launch(void* const* d_in, const int* in_sizes, int n_in,
                              void* d_out, int out_size) {
  const float* hidden = (const float*)d_in[0];
  const float* Wq = (const float*)d_in[1];
  const float* Wk = (const float*)d_in[2];
  const float* Wv = (const float*)d_in[3];
  const float* Wo = (const float*)d_in[4];
  const float* w1 = (const float*)d_in[5];
  const float* w2 = (const float*)d_in[6];
  const float* w3 = (const float*)d_in[7];
  const float* ln1 = (const float*)d_in[8];
  const float* ln2 = (const float*)d_in[9];
  float* out = (float*)d_out;

  float *p_qf, *p_kf, *p_h, *p_g1, *p_g3;
  __nv_bfloat16 *p_xnh, *p_xnl, *p_qh, *p_ql, *p_kh, *p_kl, *p_vb;
  __nv_bfloat16 *p_ch, *p_cl, *p_ynh, *p_ynl, *p_th, *p_tl, *p_wth, *p_wtl;
  cudaGetSymbolAddress((void**)&p_qf, g_qf);
  cudaGetSymbolAddress((void**)&p_kf, g_kf);
  cudaGetSymbolAddress((void**)&p_h, g_h);
  cudaGetSymbolAddress((void**)&p_g1, g_g1);
  cudaGetSymbolAddress((void**)&p_g3, g_g3);
  cudaGetSymbolAddress((void**)&p_xnh, g_xnh);
  cudaGetSymbolAddress((void**)&p_xnl, g_xnl);
  cudaGetSymbolAddress((void**)&p_qh, g_qh);
  cudaGetSymbolAddress((void**)&p_ql, g_ql);
  cudaGetSymbolAddress((void**)&p_kh, g_kh);
  cudaGetSymbolAddress((void**)&p_kl, g_kl);
  cudaGetSymbolAddress((void**)&p_vb, g_vb);
  cudaGetSymbolAddress((void**)&p_ch, g_ch);
  cudaGetSymbolAddress((void**)&p_cl, g_cl);
  cudaGetSymbolAddress((void**)&p_ynh, g_ynh);
  cudaGetSymbolAddress((void**)&p_ynl, g_ynl);
  cudaGetSymbolAddress((void**)&p_th, g_th);
  cudaGetSymbolAddress((void**)&p_tl, g_tl);
  cudaGetSymbolAddress((void**)&p_wth, g_wth);
  cudaGetSymbolAddress((void**)&p_wtl, g_wtl);

  static bool attr_set = false;
  if (!attr_set) {
    cudaFuncSetAttribute(flash_mma_kernel,
                         cudaFuncAttributeMaxDynamicSharedMemorySize, FA_SMEM);
    cudaFuncSetAttribute(gemm_tc_kernel<false>,
                         cudaFuncAttributeMaxDynamicSharedMemorySize, GEMM_SMEM);
    cudaFuncSetAttribute(gemm_tc_kernel<true>,
                         cudaFuncAttributeMaxDynamicSharedMemorySize, GEMM_SMEM);
    attr_set = true;
  }

  __nv_bfloat16* wh[7];
  __nv_bfloat16* wl[7];
  for (int i = 0; i < 7; i++) {
    wh[i] = p_wth + (size_t)i * N2;
    wl[i] = p_wtl + (size_t)i * N2;
  }
  const float* wsrc[7] = {Wq, Wk, Wv, Wo, w1, w3, w2};

  WPack wp;
  for (int i = 0; i < 7; i++) {
    wp.src[i] = wsrc[i];
    wp.oh[i] = wh[i];
    wp.ol[i] = wl[i];
  }
  transpose_split_all<<<dim3(64, 64, 7), dim3(32, 8)>>>(wp);

  rmsnorm_split_kernel<<<MROWS, 256>>>(hidden, ln1, p_xnh, p_xnl);
  rope_table_kernel<<<(SEQ * 64) / 256, 256>>>();

  // QKV projections (z=3); z==2 (V) written directly as bf16
  dim3 qkv_grid(HID / BN, MROWS / BM, 3);
  gemm_tc_kernel<false><<<qkv_grid, 256, GEMM_SMEM>>>(
      p_xnh, p_xnl, wh[0], wl[0], wh[1], wl[1], wh[2], wl[2],
      nullptr, p_qf, p_kf, nullptr, p_vb);

  rope_split_kernel<<<(MROWS * NH * 64) / 256, 256>>>(
      p_qf, p_kf, p_qh, p_ql, p_kh, p_kl);

  flash_mma_kernel<<<dim3(SEQ / 64, BATCH * NH), 128, FA_SMEM>>>(
      p_qh, p_ql, p_kh, p_kl, p_vb, p_ch, p_cl);

  // Output projection + residual
  dim3 g1_grid(HID / BN, MROWS / BM, 1);
  gemm_tc_kernel<true><<<g1_grid, 256, GEMM_SMEM>>>(
      p_ch, p_cl, wh[3], wl[3], nullptr, nullptr, nullptr, nullptr,
      hidden, p_h, nullptr, nullptr, nullptr);

  rmsnorm_split_kernel<<<MROWS, 256>>>(p_h, ln2, p_ynh, p_ynl);

  // MLP up + gate (z=2)
  dim3 g2_grid(HID / BN, MROWS / BM, 2);
  gemm_tc_kernel<false><<<g2_grid, 256, GEMM_SMEM>>>(
      p_ynh, p_ynl, wh[4], wl[4], wh[5], wl[5], nullptr, nullptr,
      nullptr, p_g1, p_g3, nullptr, nullptr);

  silumul_split_kernel<<<(MROWS * HID / 4) / 256, 256>>>(p_g1, p_g3, p_th, p_tl);

  // Down projection + residual -> output
  gemm_tc_kernel<true><<<g1_grid, 256, GEMM_SMEM>>>(
      p_th, p_tl, wh[6], wl[6], nullptr, nullptr, nullptr, nullptr,
      p_h, out, nullptr, nullptr, nullptr);
}

// round 7
// speedup vs baseline: 4.0270x; 1.1810x over previous
#include <cuda_runtime.h>
#include <cuda_bf16.h>
#include <math.h>
#include <stdint.h>

// ---------------------------------------------------------------------------
// Problem constants: B=2, S=2048, HID=2048, NH=16, HD=128, fp32 in/out.
// ---------------------------------------------------------------------------
#define BATCH 2
#define SEQ   2048
#define HID   2048
#define NH    16
#define HD    128
#define MROWS (BATCH * SEQ)
#define EPS   1e-6f
#define N2    (HID * HID)

// ---------------------------------------------------------------------------
// Scratch (device globals). Activations are tf32-rounded fp32 where consumed
// by tf32 mma; V/P path stays bf16.
// ---------------------------------------------------------------------------
__device__ float g_xn [MROWS * HID];
__device__ float g_q  [MROWS * HID];
__device__ float g_k  [MROWS * HID];
__device__ float g_ctx[MROWS * HID];
__device__ float g_h  [MROWS * HID];
__device__ float g_yn [MROWS * HID];
__device__ float g_g1 [MROWS * HID];
__device__ float g_g3 [MROWS * HID];
__device__ float g_t  [MROWS * HID];
__device__ float g_wt [7 * N2];            // transposed tf32 weights [N][K]
__device__ __nv_bfloat16 g_vb[MROWS * HID];
__device__ float g_cos[SEQ * (HD / 2)];
__device__ float g_sin[SEQ * (HD / 2)];

// ---------------------------------------------------------------------------
// PTX helpers
// ---------------------------------------------------------------------------
__device__ __forceinline__ uint32_t smem_u32(const void* p) {
  uint32_t a;
  asm("{ .reg .u64 t; cvta.to.shared.u64 t, %1; cvt.u32.u64 %0, t; }"
      : "=r"(a) : "l"(p));
  return a;
}
__device__ __forceinline__ void ldsm_x4(uint32_t (&r)[4], uint32_t addr) {
  asm volatile("ldmatrix.sync.aligned.m8n8.x4.shared.b16 {%0,%1,%2,%3}, [%4];"
               : "=r"(r[0]), "=r"(r[1]), "=r"(r[2]), "=r"(r[3]) : "r"(addr));
}
__device__ __forceinline__ void ldsm_x4_t(uint32_t (&r)[4], uint32_t addr) {
  asm volatile("ldmatrix.sync.aligned.m8n8.x4.trans.shared.b16 {%0,%1,%2,%3}, [%4];"
               : "=r"(r[0]), "=r"(r[1]), "=r"(r[2]), "=r"(r[3]) : "r"(addr));
}
// bf16 mma (used for P*V in flash)
__device__ __forceinline__ void mma16816(float (&d)[4], const uint32_t (&a)[4],
                                         const uint32_t b0, const uint32_t b1) {
  asm volatile(
      "mma.sync.aligned.m16n8k16.row.col.f32.bf16.bf16.f32 "
      "{%0,%1,%2,%3}, {%4,%5,%6,%7}, {%8,%9}, {%0,%1,%2,%3};"
      : "+f"(d[0]), "+f"(d[1]), "+f"(d[2]), "+f"(d[3])
      : "r"(a[0]), "r"(a[1]), "r"(a[2]), "r"(a[3]), "r"(b0), "r"(b1));
}
// tf32 mma m16n8k8
__device__ __forceinline__ void mma_tf32(float (&d)[4], const uint32_t (&a)[4],
                                         const uint32_t b0, const uint32_t b1) {
  asm volatile(
      "mma.sync.aligned.m16n8k8.row.col.f32.tf32.tf32.f32 "
      "{%0,%1,%2,%3}, {%4,%5,%6,%7}, {%8,%9}, {%0,%1,%2,%3};"
      : "+f"(d[0]), "+f"(d[1]), "+f"(d[2]), "+f"(d[3])
      : "r"(a[0]), "r"(a[1]), "r"(a[2]), "r"(a[3]), "r"(b0), "r"(b1));
}
__device__ __forceinline__ void cp16(uint32_t dst, const void* src) {
  asm volatile("cp.async.cg.shared.global [%0], [%1], 16;"
               :: "r"(dst), "l"(src));
}
#define CP_COMMIT asm volatile("cp.async.commit_group;" ::: "memory")
#define CP_WAIT0  asm volatile("cp.async.wait_group 0;" ::: "memory")
#define CP_WAIT1  asm volatile("cp.async.wait_group 1;" ::: "memory")

// tf32 round-to-nearest: destination of cvt.*.tf32.f32 is a b32 register.
__device__ __forceinline__ float rna_tf32(float x) {
  uint32_t o;
  asm("cvt.rna.tf32.f32 %0, %1;" : "=r"(o) : "f"(x));
  return __uint_as_float(o);
}
__device__ __forceinline__ uint32_t packbf(float a, float b) {
  __nv_bfloat162 p = __floats2bfloat162_rn(a, b);
  return *reinterpret_cast<uint32_t*>(&p);
}

// ---------------------------------------------------------------------------
// TF32 GEMM: C[M,N] = A @ B^T (+D). A[M,K], B[N,K] tf32-rounded fp32.
// CTA 128x128, KC=64, 8 warps (2Mx4N), warp tile 64x32, cp.async 2-stage.
// blockIdx.z selects among up to 3 (B, C) pairs sharing A. z==2 with Vb2
// writes bf16 output (V path).
// ---------------------------------------------------------------------------
#define BM 128
#define BN 128
#define KC 64
#define SAB 272                       // 64 tf32 (256B) + 16B pad
#define PLANE_BYTES (128 * SAB)       // 34816
#define STAGE_BYTES (2 * PLANE_BYTES) // A | B
#define GEMM_SMEM (2 * STAGE_BYTES)   // 139264

template <bool ADD>
__global__ void __launch_bounds__(256) gemm_tc_kernel(
    const float* __restrict__ A,
    const float* __restrict__ B0, const float* __restrict__ B1,
    const float* __restrict__ B2,
    const float* __restrict__ Dres,
    float* __restrict__ C0, float* __restrict__ C1, float* __restrict__ C2,
    __nv_bfloat16* __restrict__ Vb2) {
  const float* Bp = (blockIdx.z == 0) ? B0 : (blockIdx.z == 1 ? B1 : B2);
  float* C = (blockIdx.z == 0) ? C0 : (blockIdx.z == 1 ? C1 : C2);
  __nv_bfloat16* Cb = (blockIdx.z == 2) ? Vb2 : nullptr;

  extern __shared__ char sm[];
  uint32_t sbase = smem_u32(sm);

  int tid  = threadIdx.x;
  int lane = tid & 31;
  int wid  = tid >> 5;
  int wm   = wid & 1;
  int wn   = wid >> 1;
  int m0 = blockIdx.y * BM;
  int n0 = blockIdx.x * BN;

  const float* Ag = A  + (size_t)m0 * HID;
  const float* Bg = Bp + (size_t)n0 * HID;

  float acc[4][4][4];
#pragma unroll
  for (int i = 0; i < 4; i++)
#pragma unroll
    for (int j = 0; j < 4; j++)
#pragma unroll
      for (int q = 0; q < 4; q++) acc[i][j][q] = 0.f;

  // copy one chunk (A plane + B plane) into stage s via cp.async
#define STAGE_A(s, c) do {                                                    \
    uint32_t abase = sbase + (s) * STAGE_BYTES;                               \
    uint32_t bbase = abase + PLANE_BYTES;                                     \
    int kc = (c) * KC;                                                        \
    _Pragma("unroll")                                                         \
    for (int it = 0; it < 8; ++it) {                                          \
      int idx = it * 256 + tid;                                               \
      int r = idx >> 4, g = idx & 15;                                         \
      cp16(abase + r * SAB + g * 16, Ag + (size_t)r * HID + kc + g * 4);      \
      cp16(bbase + r * SAB + g * 16, Bg + (size_t)r * HID + kc + g * 4);      \
    }                                                                         \
  } while (0)

  // fragment lane addressing (b16-view columns)
  int a_row = wm * 64 + (lane & 15);
  int a_col8 = (lane >> 4) << 3;
  int b_row = wn * 32 + ((lane >> 4) << 3) + (lane & 7);
  int b_col8 = ((lane >> 3) & 1) << 3;

  STAGE_A(0, 0);
  CP_COMMIT;

  const int NCHUNK = HID / KC;
  int stage = 0;

  for (int c = 0; c < NCHUNK; ++c) {
    if (c + 1 < NCHUNK) {
      STAGE_A(stage ^ 1, c + 1);
      CP_COMMIT;
      CP_WAIT1;
    } else {
      CP_WAIT0;
    }
    __syncthreads();

    uint32_t pA = sbase + stage * STAGE_BYTES;
    uint32_t pB = pA + PLANE_BYTES;

#pragma unroll
    for (int k8 = 0; k8 < 8; ++k8) {
      uint32_t af[4][4];
#pragma unroll
      for (int mi = 0; mi < 4; ++mi)
        ldsm_x4(af[mi], pA + (uint32_t)((a_row + mi * 16) * SAB +
                                        (k8 * 16 + a_col8) * 2));
      uint32_t bf_[2][4];
#pragma unroll
      for (int nj = 0; nj < 2; ++nj)
        ldsm_x4(bf_[nj], pB + (uint32_t)((b_row + nj * 16) * SAB +
                                         (k8 * 16 + b_col8) * 2));
#pragma unroll
      for (int mi = 0; mi < 4; ++mi) {
        mma_tf32(acc[mi][0], af[mi], bf_[0][0], bf_[0][1]);
        mma_tf32(acc[mi][1], af[mi], bf_[0][2], bf_[0][3]);
        mma_tf32(acc[mi][2], af[mi], bf_[1][0], bf_[1][1]);
        mma_tf32(acc[mi][3], af[mi], bf_[1][2], bf_[1][3]);
      }
    }
    __syncthreads();
    stage ^= 1;
  }
#undef STAGE_A

  int er = m0 + wm * 64 + (lane >> 2);
  int ec = n0 + wn * 32 + (lane & 3) * 2;
#pragma unroll
  for (int mi = 0; mi < 4; ++mi) {
#pragma unroll
    for (int nt = 0; nt < 4; ++nt) {
      size_t o0 = (size_t)(er + mi * 16) * HID + ec + nt * 8;
      size_t o1 = o0 + 8 * HID;
      if (Cb) {
        *(uint32_t*)(Cb + o0) = packbf(acc[mi][nt][0], acc[mi][nt][1]);
        *(uint32_t*)(Cb + o1) = packbf(acc[mi][nt][2], acc[mi][nt][3]);
      } else {
        float2 v0 = make_float2(acc[mi][nt][0], acc[mi][nt][1]);
        float2 v1 = make_float2(acc[mi][nt][2], acc[mi][nt][3]);
        if (ADD) {
          float2 d0 = *(const float2*)(Dres + o0);
          float2 d1 = *(const float2*)(Dres + o1);
          v0.x += d0.x; v0.y += d0.y;
          v1.x += d1.x; v1.y += d1.y;
        }
        *(float2*)(C + o0) = v0;
        *(float2*)(C + o1) = v1;
      }
    }
  }
}

// ---------------------------------------------------------------------------
// Flash attention: QK^T in tf32 (1 pass), P*V in bf16. 64 q-rows/CTA,
// 4 warps, BN=64, HD=128, cp.async 2-stage K(fp32)+V(bf16).
// ---------------------------------------------------------------------------
#define KROWB 528                       // 128 tf32 (512B) + 16 pad
#define VROWB 272                       // 128 bf16 (256B) + 16 pad
#define KPL (64 * KROWB)                // 33792
#define VPL (64 * VROWB)                // 17408
#define FA_STAGE_BYTES (KPL + VPL)      // 51200
#define FA_SMEM (2 * FA_STAGE_BYTES)    // 102400

__global__ void __launch_bounds__(128) flash_mma_kernel(
    const float* __restrict__ qf, const float* __restrict__ kf,
    const __nv_bfloat16* __restrict__ vb, float* __restrict__ ctx) {
  extern __shared__ char smc[];
  uint32_t pS = smem_u32(smc);

  int qb = blockIdx.x;
  int bh = blockIdx.y;
  int b = bh >> 4, h = bh & 15;
  int tid = threadIdx.x;
  int lane = tid & 31;
  int w = tid >> 5;
  int colbase = h * HD;
  size_t row0 = (size_t)b * SEQ + qb * 64;

  // ---- stage Q (fp32, tf32-rounded already) and load 16 k8 fragments ----
  uint32_t qfr[16][4];
  {
    char* sQ = smc;
#pragma unroll
    for (int it = 0; it < 16; ++it) {
      int idx = it * 128 + tid;
      int r = idx >> 5, g = idx & 31;
      *(uint4*)(sQ + r * KROWB + g * 16) =
          *(const uint4*)(qf + (row0 + r) * HID + colbase + g * 4);
    }
    __syncthreads();
    uint32_t qaddr = pS + (uint32_t)((w * 16 + (lane & 15)) * KROWB +
                                     ((lane >> 4) << 3) * 2);
#pragma unroll
    for (int k8 = 0; k8 < 16; ++k8) ldsm_x4(qfr[k8], qaddr + k8 * 32);
    __syncthreads();
  }

#define FA_PREFETCH(st, nb) do {                                              \
    size_t krow = (size_t)b * SEQ + (size_t)(nb) * 64;                        \
    uint32_t stb = pS + (st) * FA_STAGE_BYTES;                                \
    _Pragma("unroll")                                                         \
    for (int it = 0; it < 16; ++it) {                                         \
      int idx = it * 128 + tid;                                               \
      int r = idx >> 5, g = idx & 31;                                         \
      cp16(stb + r * KROWB + g * 16,                                          \
           kf + (krow + r) * HID + colbase + g * 4);                          \
    }                                                                         \
    _Pragma("unroll")                                                         \
    for (int it = 0; it < 8; ++it) {                                          \
      int idx = it * 128 + tid;                                               \
      int r = idx >> 4, g = idx & 15;                                         \
      cp16(stb + KPL + r * VROWB + g * 16,                                    \
           vb + (krow + r) * HID + colbase + g * 8);                          \
    }                                                                         \
  } while (0)

  float O[16][4];
#pragma unroll
  for (int j = 0; j < 16; ++j)
#pragma unroll
    for (int q = 0; q < 4; ++q) O[j][q] = 0.f;
  float m0 = -INFINITY, m1 = -INFINITY, l0 = 0.f, l1 = 0.f;
  const float scale = 0.08838834764831845f;

  int b_row = ((lane >> 4) << 3) + (lane & 7);
  int b_col8 = ((lane >> 3) & 1) << 3;

  FA_PREFETCH(0, 0);
  CP_COMMIT;

  const int NB = SEQ / 64;
  int st = 0;

  for (int nb = 0; nb < NB; ++nb) {
    if (nb + 1 < NB) {
      FA_PREFETCH(st ^ 1, nb + 1);
      CP_COMMIT;
      CP_WAIT1;
    } else {
      CP_WAIT0;
    }
    __syncthreads();

    uint32_t pK = pS + st * FA_STAGE_BYTES;
    uint32_t pV = pK + KPL;

    // ---- S = Q K^T (tf32, single pass) ----
    float S[8][4];
#pragma unroll
    for (int j = 0; j < 8; ++j)
#pragma unroll
      for (int q = 0; q < 4; ++q) S[j][q] = 0.f;

#pragma unroll
    for (int k8 = 0; k8 < 16; ++k8) {
#pragma unroll
      for (int nj = 0; nj < 4; ++nj) {
        uint32_t rb[4];
        ldsm_x4(rb, pK + (uint32_t)((nj * 16 + b_row) * KROWB +
                                    (k8 * 16 + b_col8) * 2));
        mma_tf32(S[2 * nj],     qfr[k8], rb[0], rb[1]);
        mma_tf32(S[2 * nj + 1], qfr[k8], rb[2], rb[3]);
      }
    }

    // ---- online softmax ----
#pragma unroll
    for (int j = 0; j < 8; ++j)
#pragma unroll
      for (int q = 0; q < 4; ++q) S[j][q] *= scale;

    float mr0 = -INFINITY, mr1 = -INFINITY;
#pragma unroll
    for (int j = 0; j < 8; ++j) {
      mr0 = fmaxf(mr0, fmaxf(S[j][0], S[j][1]));
      mr1 = fmaxf(mr1, fmaxf(S[j][2], S[j][3]));
    }
    mr0 = fmaxf(mr0, __shfl_xor_sync(0xffffffffu, mr0, 1));
    mr0 = fmaxf(mr0, __shfl_xor_sync(0xffffffffu, mr0, 2));
    mr1 = fmaxf(mr1, __shfl_xor_sync(0xffffffffu, mr1, 1));
    mr1 = fmaxf(mr1, __shfl_xor_sync(0xffffffffu, mr1, 2));

    float mn0 = fmaxf(m0, mr0), mn1 = fmaxf(m1, mr1);
    float a0 = __expf(m0 - mn0), a1 = __expf(m1 - mn1);
    float s0 = 0.f, s1 = 0.f;
#pragma unroll
    for (int j = 0; j < 8; ++j) {
      S[j][0] = __expf(S[j][0] - mn0);
      S[j][1] = __expf(S[j][1] - mn0);
      S[j][2] = __expf(S[j][2] - mn1);
      S[j][3] = __expf(S[j][3] - mn1);
      s0 += S[j][0] + S[j][1];
      s1 += S[j][2] + S[j][3];
    }
    s0 += __shfl_xor_sync(0xffffffffu, s0, 1);
    s0 += __shfl_xor_sync(0xffffffffu, s0, 2);
    s1 += __shfl_xor_sync(0xffffffffu, s1, 1);
    s1 += __shfl_xor_sync(0xffffffffu, s1, 2);

    l0 = l0 * a0 + s0;
    l1 = l1 * a1 + s1;
    m0 = mn0; m1 = mn1;

#pragma unroll
    for (int j = 0; j < 16; ++j) {
      O[j][0] *= a0; O[j][1] *= a0;
      O[j][2] *= a1; O[j][3] *= a1;
    }

    uint32_t pf[4][4];
#pragma unroll
    for (int t = 0; t < 4; ++t) {
      pf[t][0] = packbf(S[2 * t][0],     S[2 * t][1]);
      pf[t][1] = packbf(S[2 * t][2],     S[2 * t][3]);
      pf[t][2] = packbf(S[2 * t + 1][0], S[2 * t + 1][1]);
      pf[t][3] = packbf(S[2 * t + 1][2], S[2 * t + 1][3]);
    }

#pragma unroll
    for (int t = 0; t < 4; ++t) {
#pragma unroll
      for (int n16 = 0; n16 < 8; ++n16) {
        uint32_t voff = (uint32_t)((t * 16 + (lane & 15)) * VROWB +
                                   (n16 * 16 + ((lane >> 4) << 3)) * 2);
        uint32_t rv[4];
        ldsm_x4_t(rv, pV + voff);
        mma16816(O[2 * n16],     pf[t], rv[0], rv[1]);
        mma16816(O[2 * n16 + 1], pf[t], rv[2], rv[3]);
      }
    }
    __syncthreads();
    st ^= 1;
  }
#undef FA_PREFETCH

  // ---- epilogue: normalize, tf32-round, write fp32 ctx ----
  float i0 = 1.0f / l0, i1 = 1.0f / l1;
  int r = lane >> 2, c2 = (lane & 3) * 2;
  size_t gr0 = row0 + w * 16 + r;
#pragma unroll
  for (int j = 0; j < 16; ++j) {
    int col = colbase + j * 8 + c2;
    float2 v0 = make_float2(rna_tf32(O[j][0] * i0), rna_tf32(O[j][1] * i0));
    float2 v1 = make_float2(rna_tf32(O[j][2] * i1), rna_tf32(O[j][3] * i1));
    *(float2*)(ctx + gr0 * HID + col) = v0;
    *(float2*)(ctx + (gr0 + 8) * HID + col) = v1;
  }
}

// ---------------------------------------------------------------------------
// All-weights transpose (+ tf32 round) in one launch (z = weight index)
// ---------------------------------------------------------------------------
struct WPack {
  const float* src[7];
  float* dst[7];
};

__global__ void __launch_bounds__(256) transpose_all(WPack p) {
  const float* in = p.src[blockIdx.z];
  float* out = p.dst[blockIdx.z];
  __shared__ float t[32][33];
  int tx = threadIdx.x, ty = threadIdx.y;
  int x = blockIdx.x * 32 + tx;
  int y0 = blockIdx.y * 32;
#pragma unroll
  for (int i = ty; i < 32; i += 8)
    t[i][tx] = in[(size_t)(y0 + i) * HID + x];
  __syncthreads();
  int ox = y0 + tx;
  int oy0 = blockIdx.x * 32;
#pragma unroll
  for (int i = ty; i < 32; i += 8)
    out[(size_t)(oy0 + i) * HID + ox] = rna_tf32(t[tx][i]);
}

// ---------------------------------------------------------------------------
// RMSNorm -> tf32-rounded fp32
// ---------------------------------------------------------------------------
__global__ void __launch_bounds__(256) rmsnorm_kernel(
    const float* __restrict__ x, const float* __restrict__ w,
    float* __restrict__ y) {
  int row = blockIdx.x;
  const float4* x4 = (const float4*)(x + (size_t)row * HID);
  const float4* w4 = (const float4*)w;
  float4* y4 = (float4*)(y + (size_t)row * HID);
  int tid = threadIdx.x;

  float s = 0.f;
#pragma unroll
  for (int i = tid; i < HID / 4; i += 256) {
    float4 v = x4[i];
    s += v.x * v.x + v.y * v.y + v.z * v.z + v.w * v.w;
  }
#pragma unroll
  for (int off = 16; off > 0; off >>= 1)
    s += __shfl_xor_sync(0xffffffffu, s, off);

  __shared__ float red[8];
  __shared__ float s_inv;
  if ((tid & 31) == 0) red[tid >> 5] = s;
  __syncthreads();
  if (tid == 0) {
    float t = 0.f;
#pragma unroll
    for (int i = 0; i < 8; i++) t += red[i];
    s_inv = rsqrtf(t / (float)HID + EPS);
  }
  __syncthreads();
  float inv = s_inv;

#pragma unroll
  for (int i = tid; i < HID / 4; i += 256) {
    float4 v = x4[i];
    float4 ww = w4[i];
    float4 o;
    o.x = rna_tf32(v.x * inv * ww.x);
    o.y = rna_tf32(v.y * inv * ww.y);
    o.z = rna_tf32(v.z * inv * ww.z);
    o.w = rna_tf32(v.w * inv * ww.w);
    y4[i] = o;
  }
}

// ---------------------------------------------------------------------------
// RoPE table + apply (in-place, tf32 rounding)
// ---------------------------------------------------------------------------
__global__ void rope_table_kernel() {
  int idx = blockIdx.x * 256 + threadIdx.x;
  int s = idx >> 6;
  int d = idx & 63;
  float invf = 1.0f / powf(10000.0f, (float)d / 64.0f);
  float ang = (float)s * invf;
  g_cos[idx] = cosf(ang);
  g_sin[idx] = sinf(ang);
}

__global__ void __launch_bounds__(256) rope_kernel(
    float* __restrict__ q, float* __restrict__ k) {
  int idx = blockIdx.x * 256 + threadIdx.x;
  int d = idx & 63;
  int h = (idx >> 6) & 15;
  int row = idx >> 10;
  int s = row & (SEQ - 1);

  float c  = g_cos[s * 64 + d];
  float sn = g_sin[s * 64 + d];
  size_t base = (size_t)row * HID + h * HD + d;

  float q1 = q[base], q2 = q[base + 64];
  q[base]      = rna_tf32(q1 * c - q2 * sn);
  q[base + 64] = rna_tf32(q2 * c + q1 * sn);

  float k1 = k[base], k2 = k[base + 64];
  k[base]      = rna_tf32(k1 * c - k2 * sn);
  k[base + 64] = rna_tf32(k2 * c + k1 * sn);
}

// ---------------------------------------------------------------------------
// SiLU(g1)*g3 -> tf32-rounded fp32
// ---------------------------------------------------------------------------
__global__ void __launch_bounds__(256) silumul_kernel(
    const float* __restrict__ a, const float* __restrict__ b,
    float* __restrict__ c) {
  int idx = blockIdx.x * 256 + threadIdx.x;
  float4 va = ((const float4*)a)[idx];
  float4 vb = ((const float4*)b)[idx];
  float4 vc;
  vc.x = rna_tf32(va.x / (1.f + __expf(-va.x)) * vb.x);
  vc.y = rna_tf32(va.y / (1.f + __expf(-va.y)) * vb.y);
  vc.z = rna_tf32(va.z / (1.f + __expf(-va.z)) * vb.z);
  vc.w = rna_tf32(va.w / (1.f + __expf(-va.w)) * vb.w);
  ((float4*)c)[idx] = vc;
}

// ---------------------------------------------------------------------------
// Launch
// ---------------------------------------------------------------------------
extern "C" void kernel_launch(void* const* d_in, const int* in_sizes, int n_in,
                              void* d_out, int out_size) {
  const float* hidden = (const float*)d_in[0];
  const float* Wq = (const float*)d_in[1];
  const float* Wk = (const float*)d_in[2];
  const float* Wv = (const float*)d_in[3];
  const float* Wo = (const float*)d_in[4];
  const float* w1 = (const float*)d_in[5];
  const float* w2 = (const float*)d_in[6];
  const float* w3 = (const float*)d_in[7];
  const float* ln1 = (const float*)d_in[8];
  const float* ln2 = (const float*)d_in[9];
  float* out = (float*)d_out;

  float *p_xn, *p_q, *p_k, *p_ctx, *p_h, *p_yn, *p_g1, *p_g3, *p_t, *p_wt;
  __nv_bfloat16* p_vb;
  cudaGetSymbolAddress((void**)&p_xn, g_xn);
  cudaGetSymbolAddress((void**)&p_q, g_q);
  cudaGetSymbolAddress((void**)&p_k, g_k);
  cudaGetSymbolAddress((void**)&p_ctx, g_ctx);
  cudaGetSymbolAddress((void**)&p_h, g_h);
  cudaGetSymbolAddress((void**)&p_yn, g_yn);
  cudaGetSymbolAddress((void**)&p_g1, g_g1);
  cudaGetSymbolAddress((void**)&p_g3, g_g3);
  cudaGetSymbolAddress((void**)&p_t, g_t);
  cudaGetSymbolAddress((void**)&p_wt, g_wt);
  cudaGetSymbolAddress((void**)&p_vb, g_vb);

  static bool attr_set = false;
  if (!attr_set) {
    cudaFuncSetAttribute(flash_mma_kernel,
                         cudaFuncAttributeMaxDynamicSharedMemorySize, FA_SMEM);
    cudaFuncSetAttribute(gemm_tc_kernel<false>,
                         cudaFuncAttributeMaxDynamicSharedMemorySize, GEMM_SMEM);
    cudaFuncSetAttribute(gemm_tc_kernel<true>,
                         cudaFuncAttributeMaxDynamicSharedMemorySize, GEMM_SMEM);
    attr_set = true;
  }

  float* wt[7];
  for (int i = 0; i < 7; i++) wt[i] = p_wt + (size_t)i * N2;
  const float* wsrc[7] = {Wq, Wk, Wv, Wo, w1, w3, w2};

  WPack wp;
  for (int i = 0; i < 7; i++) {
    wp.src[i] = wsrc[i];
    wp.dst[i] = wt[i];
  }
  transpose_all<<<dim3(64, 64, 7), dim3(32, 8)>>>(wp);

  rmsnorm_kernel<<<MROWS, 256>>>(hidden, ln1, p_xn);
  rope_table_kernel<<<(SEQ * 64) / 256, 256>>>();

  // QKV projections (z=3); z==2 (V) written directly as bf16
  dim3 qkv_grid(HID / BN, MROWS / BM, 3);
  gemm_tc_kernel<false><<<qkv_grid, 256, GEMM_SMEM>>>(
      p_xn, wt[0], wt[1], wt[2], nullptr, p_q, p_k, nullptr, p_vb);

  rope_kernel<<<(MROWS * NH * 64) / 256, 256>>>(p_q, p_k);

  flash_mma_kernel<<<dim3(SEQ / 64, BATCH * NH), 128, FA_SMEM>>>(
      p_q, p_k, p_vb, p_ctx);

  // Output projection + residual
  dim3 g1_grid(HID / BN, MROWS / BM, 1);
  gemm_tc_kernel<true><<<g1_grid, 256, GEMM_SMEM>>>(
      p_ctx, wt[3], nullptr, nullptr, hidden, p_h, nullptr, nullptr, nullptr);

  rmsnorm_kernel<<<MROWS, 256>>>(p_h, ln2, p_yn);

  // MLP up + gate (z=2)
  dim3 g2_grid(HID / BN, MROWS / BM, 2);
  gemm_tc_kernel<false><<<g2_grid, 256, GEMM_SMEM>>>(
      p_yn, wt[4], wt[5], nullptr, nullptr, p_g1, p_g3, nullptr, nullptr);

  silumul_kernel<<<(MROWS * HID / 4) / 256, 256>>>(p_g1, p_g3, p_t);

  // Down projection + residual -> output
  gemm_tc_kernel<true><<<g1_grid, 256, GEMM_SMEM>>>(
      p_t, wt[6], nullptr, nullptr, p_h, out, nullptr, nullptr, nullptr);
}